// round 1
// baseline (speedup 1.0000x reference)
#include <cuda_runtime.h>
#include <math.h>

// Fixed problem shape (dataset shape is fixed; B derived at runtime, max 4)
#define Hc  256
#define Wc  256
#define CIN 128
#define BR  64
#define HWC (Hc * Wc)
#define CK  4          // input channels per smem chunk

// ---------------- scratch (static device globals; no runtime allocation) ----
__device__ float g_f[(size_t)4 * 128 * Hc * Wc];   // 128 MB: post-BN branch features [B,128,H,W]
__device__ float g_att[(size_t)4 * 2 * Hc * Wc];   // 2 MB: post-BN attention logits [B,2,H,W]

// position helpers: matches _generate_position_info + _linear_map
__device__ __forceinline__ float axis_g(int i, int n) {
    float off = ((n & 1) == 0) ? 0.5f : 0.0f;
    return fabsf((float)i - (float)(n / 2) + off) / (float)(n / 2);
}

// ============================================================================
// Kernel 1: combined 3x3 conv (128 -> 128) + bias + folded BN  ->  g_f
//   grid = (H, 2, B); block = 256 threads
//   block computes one output row (256 px) for 64 channels (one branch half)
//   thread tile: 8 channels x 8 pixels (pixels strided by 32 -> conflict-free LDS)
// ============================================================================
__global__ __launch_bounds__(256, 2)
void conv_bn_kernel(const float* __restrict__ x,
                    const float* __restrict__ wa, const float* __restrict__ ba,
                    const float* __restrict__ wb, const float* __restrict__ bbv,
                    const float* __restrict__ gA, const float* __restrict__ beA,
                    const float* __restrict__ mA, const float* __restrict__ vA,
                    const float* __restrict__ gB, const float* __restrict__ beB,
                    const float* __restrict__ mB, const float* __restrict__ vB)
{
    __shared__ float s_in[CK][3][264];   // cols 0..257 <-> x = -1..256
    __shared__ float s_w[CK][9][64];     // [cin_local][ky*3+kx][oc]

    const int y    = blockIdx.x;
    const int half = blockIdx.y;         // 0 = branch a, 1 = branch b
    const int bb   = blockIdx.z;
    const int tid  = threadIdx.x;
    const int pxg  = tid & 31;           // lane: pixel group (pixels pxg + 32*i)
    const int chg  = tid >> 5;           // warp: channel group (channels chg*8 + o)

    const float* wsrc = half ? wb : wa;

    float acc[8][8];
    #pragma unroll
    for (int o = 0; o < 8; o++)
        #pragma unroll
        for (int i = 0; i < 8; i++) acc[o][i] = 0.f;

    for (int c0 = 0; c0 < CIN; c0 += CK) {
        // ---- load input rows y-1..y+1 for CK channels (zero-padded) ----
        for (int i = tid; i < CK * 3 * 258; i += 256) {
            int c_l = i / 774;
            int rem = i - c_l * 774;
            int dy  = rem / 258;
            int col = rem - dy * 258;
            int yy  = y + dy - 1;
            int xx  = col - 1;
            float v = 0.f;
            if (yy >= 0 && yy < Hc && xx >= 0 && xx < Wc)
                v = x[(((size_t)bb * CIN + c0 + c_l) * Hc + yy) * Wc + xx];
            s_in[c_l][dy][col] = v;
        }
        // ---- load weights: 64 oc x CK cin x 9 taps (contiguous 36B runs) ----
        for (int i = tid; i < CK * 9 * 64; i += 256) {
            int oc  = i / 36;
            int rem = i - oc * 36;
            int c_l = rem / 9;
            int k   = rem - c_l * 9;
            s_w[c_l][k][oc] = wsrc[(size_t)oc * (CIN * 9) + (size_t)(c0 + c_l) * 9 + k];
        }
        __syncthreads();

        // ---- accumulate ----
        for (int c_l = 0; c_l < CK; c_l++) {
            for (int dy = 0; dy < 3; dy++) {
                float rv[8][3];
                #pragma unroll
                for (int i = 0; i < 8; i++)
                    #pragma unroll
                    for (int kx = 0; kx < 3; kx++)
                        rv[i][kx] = s_in[c_l][dy][pxg + 32 * i + kx];
                #pragma unroll
                for (int kx = 0; kx < 3; kx++)
                    #pragma unroll
                    for (int o = 0; o < 8; o++) {
                        float wv = s_w[c_l][dy * 3 + kx][chg * 8 + o];
                        #pragma unroll
                        for (int i = 0; i < 8; i++)
                            acc[o][i] += wv * rv[i][kx];
                    }
            }
        }
        __syncthreads();
    }

    // ---- epilogue: bias + BN fold, write f ----
    const float* bsrc  = half ? bbv : ba;
    const float* gsrc  = half ? gB  : gA;
    const float* besrc = half ? beB : beA;
    const float* msrc  = half ? mB  : mA;
    const float* vsrc  = half ? vB  : vA;
    #pragma unroll
    for (int o = 0; o < 8; o++) {
        int lb = chg * 8 + o;                       // branch-local channel
        float bias = bsrc[lb];
        float sc   = gsrc[lb] * rsqrtf(vsrc[lb] + 1e-3f);
        float sh   = besrc[lb] - msrc[lb] * sc;
        float* fout = g_f + (((size_t)bb * 128 + half * BR + lb) * Hc + y) * Wc;
        #pragma unroll
        for (int i = 0; i < 8; i++)
            fout[pxg + 32 * i] = (acc[o][i] + bias) * sc + sh;
    }
}

// ============================================================================
// Kernel 2: 1x1 attention conv over [f(64), gh, gw] + BN  ->  g_att
// ============================================================================
__global__ void att_kernel(const float* __restrict__ aw, const float* __restrict__ abv,
                           const float* __restrict__ bw, const float* __restrict__ bbv,
                           const float* __restrict__ gA1, const float* __restrict__ beA1,
                           const float* __restrict__ mA1, const float* __restrict__ vA1,
                           const float* __restrict__ gB1, const float* __restrict__ beB1,
                           const float* __restrict__ mB1, const float* __restrict__ vB1,
                           int B)
{
    int idx = blockIdx.x * blockDim.x + threadIdx.x;
    int total = B * HWC;
    if (idx >= total) return;
    int bb  = idx / HWC;
    int pix = idx - bb * HWC;
    int y = pix / Wc;
    int xx = pix - y * Wc;

    const float* f0 = g_f + (size_t)bb * 128 * HWC + pix;
    float sa = 0.f, sb = 0.f;
    #pragma unroll 8
    for (int c = 0; c < 64; c++) {
        sa += __ldg(aw + c) * f0[(size_t)c * HWC];
        sb += __ldg(bw + c) * f0[(size_t)(c + 64) * HWC];
    }
    float ghv = axis_g(y, Hc);
    float gwv = axis_g(xx, Wc);
    sa += __ldg(aw + 64) * ghv + __ldg(aw + 65) * gwv + __ldg(abv);
    sb += __ldg(bw + 64) * ghv + __ldg(bw + 65) * gwv + __ldg(bbv);

    float scA = __ldg(gA1) * rsqrtf(__ldg(vA1) + 1e-5f);
    float scB = __ldg(gB1) * rsqrtf(__ldg(vB1) + 1e-5f);
    sa = (sa - __ldg(mA1)) * scA + __ldg(beA1);
    sb = (sb - __ldg(mB1)) * scB + __ldg(beB1);

    g_att[((size_t)bb * 2 + 0) * HWC + pix] = sa;
    g_att[((size_t)bb * 2 + 1) * HWC + pix] = sb;
}

// ============================================================================
// Kernel 3: 3x3 map conv over [att, gh, gw, pr] -> sigmoid -> scale -> out
// ============================================================================
__global__ void map_out_kernel(const float* __restrict__ wA, const float* __restrict__ wB,
                               const float* __restrict__ s1p, const float* __restrict__ s2p,
                               float* __restrict__ out, int B)
{
    int idx = blockIdx.x * blockDim.x + threadIdx.x;
    int total = B * HWC;
    if (idx >= total) return;
    int bb  = idx / HWC;
    int pix = idx - bb * HWC;
    int y = pix / Wc;
    int x = pix - y * Wc;

    // pr normalization constants (match _linear_map over the full grid)
    float ghmin = ((Hc & 1) == 0) ? 0.5f / (float)(Hc / 2) : 0.f;
    float gwmin = ((Wc & 1) == 0) ? 0.5f / (float)(Wc / 2) : 0.f;
    float ghmax = axis_g(0, Hc);
    float gwmax = axis_g(0, Wc);
    float prmin = sqrtf(ghmin * ghmin + gwmin * gwmin);
    float prmax = sqrtf(ghmax * ghmax + gwmax * gwmax);
    float kk = 2.f / (prmax - prmin);
    float cc = 1.f - prmax * kk;

    float maps[2];
    #pragma unroll
    for (int br = 0; br < 2; br++) {
        const float* w = br ? wB : wA;
        const float* ab = g_att + ((size_t)bb * 2 + br) * HWC;
        float s = 0.f;
        #pragma unroll
        for (int dy = -1; dy <= 1; dy++) {
            int yy = y + dy;
            if (yy < 0 || yy >= Hc) continue;
            float ghv = axis_g(yy, Hc);
            #pragma unroll
            for (int dx = -1; dx <= 1; dx++) {
                int xn = x + dx;
                if (xn < 0 || xn >= Wc) continue;     // zero padding of ALL channels
                float av  = ab[yy * Wc + xn];
                float gwv = axis_g(xn, Wc);
                float pr  = sqrtf(ghv * ghv + gwv * gwv);
                float prn = kk * pr + cc;
                int k = (dy + 1) * 3 + (dx + 1);
                s += __ldg(w + k)      * av
                   + __ldg(w + 9 + k)  * ghv
                   + __ldg(w + 18 + k) * gwv
                   + __ldg(w + 27 + k) * prn;
            }
        }
        float m = 1.f / (1.f + expf(-s));
        maps[br] = m * (br ? __ldg(s2p) : __ldg(s1p));
    }

    const float* f0 = g_f + (size_t)bb * 128 * HWC + pix;
    float*       o0 = out + (size_t)bb * 128 * HWC + pix;
    #pragma unroll 8
    for (int c = 0; c < 128; c++) {
        float m = (c < 64) ? maps[0] : maps[1];
        o0[(size_t)c * HWC] = f0[(size_t)c * HWC] * m;
    }
}

// ============================================================================
extern "C" void kernel_launch(void* const* d_in, const int* in_sizes, int n_in,
                              void* d_out, int out_size)
{
    const float* x        = (const float*)d_in[0];
    const float* conv_a_w = (const float*)d_in[1];
    const float* conv_a_b = (const float*)d_in[2];
    const float* conv_b_w = (const float*)d_in[3];
    const float* conv_b_b = (const float*)d_in[4];
    const float* bn_a_g   = (const float*)d_in[5];
    const float* bn_a_be  = (const float*)d_in[6];
    const float* bn_a_m   = (const float*)d_in[7];
    const float* bn_a_v   = (const float*)d_in[8];
    const float* bn_b_g   = (const float*)d_in[9];
    const float* bn_b_be  = (const float*)d_in[10];
    const float* bn_b_m   = (const float*)d_in[11];
    const float* bn_b_v   = (const float*)d_in[12];
    const float* att_a_w  = (const float*)d_in[13];
    const float* att_a_b  = (const float*)d_in[14];
    const float* att_b_w  = (const float*)d_in[15];
    const float* att_b_b  = (const float*)d_in[16];
    const float* abn_a_g  = (const float*)d_in[17];
    const float* abn_a_be = (const float*)d_in[18];
    const float* abn_a_m  = (const float*)d_in[19];
    const float* abn_a_v  = (const float*)d_in[20];
    const float* abn_b_g  = (const float*)d_in[21];
    const float* abn_b_be = (const float*)d_in[22];
    const float* abn_b_m  = (const float*)d_in[23];
    const float* abn_b_v  = (const float*)d_in[24];
    const float* attn_a_w = (const float*)d_in[25];
    const float* attn_b_w = (const float*)d_in[26];
    const float* scale1   = (const float*)d_in[27];
    const float* scale2   = (const float*)d_in[28];

    int B = in_sizes[0] / (CIN * Hc * Wc);

    dim3 g1(Hc, 2, B);
    conv_bn_kernel<<<g1, 256>>>(x, conv_a_w, conv_a_b, conv_b_w, conv_b_b,
                                bn_a_g, bn_a_be, bn_a_m, bn_a_v,
                                bn_b_g, bn_b_be, bn_b_m, bn_b_v);

    int total = B * HWC;
    int nb = (total + 255) / 256;
    att_kernel<<<nb, 256>>>(att_a_w, att_a_b, att_b_w, att_b_b,
                            abn_a_g, abn_a_be, abn_a_m, abn_a_v,
                            abn_b_g, abn_b_be, abn_b_m, abn_b_v, B);

    map_out_kernel<<<nb, 256>>>(attn_a_w, attn_b_w, scale1, scale2,
                                (float*)d_out, B);
}

// round 2
// speedup vs baseline: 1.0018x; 1.0018x over previous
#include <cuda_runtime.h>
#include <math.h>

// Fixed problem shape (dataset shape is fixed; B derived at runtime, max 4)
#define Hc  256
#define Wc  256
#define CIN 128
#define BR  64
#define HWC (Hc * Wc)
#define CK  4          // input channels per smem chunk

// ---------------- scratch (static device globals; no runtime allocation) ----
__device__ float g_f[(size_t)4 * 128 * Hc * Wc];   // 128 MB: post-BN branch features [B,128,H,W]
__device__ float g_att[(size_t)4 * 2 * Hc * Wc];   // 2 MB: post-BN attention logits [B,2,H,W]

// position helpers: matches _generate_position_info + _linear_map
__device__ __forceinline__ float axis_g(int i, int n) {
    float off = ((n & 1) == 0) ? 0.5f : 0.0f;
    return fabsf((float)i - (float)(n / 2) + off) / (float)(n / 2);
}

// ============================================================================
// Kernel 1: combined 3x3 conv (128 -> 128) + bias + folded BN  ->  g_f
//   grid = (H, 2, B); block = 256 threads
//   block computes one output row (256 px) for 64 channels (one branch half)
//   thread tile: 8 channels x 8 pixels (pixels strided by 32 -> conflict-free LDS)
// ============================================================================
__global__ __launch_bounds__(256, 2)
void conv_bn_kernel(const float* __restrict__ x,
                    const float* __restrict__ wa, const float* __restrict__ ba,
                    const float* __restrict__ wb, const float* __restrict__ bbv,
                    const float* __restrict__ gA, const float* __restrict__ beA,
                    const float* __restrict__ mA, const float* __restrict__ vA,
                    const float* __restrict__ gB, const float* __restrict__ beB,
                    const float* __restrict__ mB, const float* __restrict__ vB)
{
    __shared__ float s_in[CK][3][264];   // cols 0..257 <-> x = -1..256
    __shared__ float s_w[CK][9][64];     // [cin_local][ky*3+kx][oc]

    const int y    = blockIdx.x;
    const int half = blockIdx.y;         // 0 = branch a, 1 = branch b
    const int bb   = blockIdx.z;
    const int tid  = threadIdx.x;
    const int pxg  = tid & 31;           // lane: pixel group (pixels pxg + 32*i)
    const int chg  = tid >> 5;           // warp: channel group (channels chg*8 + o)

    const float* wsrc = half ? wb : wa;

    float acc[8][8];
    #pragma unroll
    for (int o = 0; o < 8; o++)
        #pragma unroll
        for (int i = 0; i < 8; i++) acc[o][i] = 0.f;

    for (int c0 = 0; c0 < CIN; c0 += CK) {
        // ---- load input rows y-1..y+1 for CK channels (zero-padded) ----
        for (int i = tid; i < CK * 3 * 258; i += 256) {
            int c_l = i / 774;
            int rem = i - c_l * 774;
            int dy  = rem / 258;
            int col = rem - dy * 258;
            int yy  = y + dy - 1;
            int xx  = col - 1;
            float v = 0.f;
            if (yy >= 0 && yy < Hc && xx >= 0 && xx < Wc)
                v = x[(((size_t)bb * CIN + c0 + c_l) * Hc + yy) * Wc + xx];
            s_in[c_l][dy][col] = v;
        }
        // ---- load weights: 64 oc x CK cin x 9 taps (contiguous 36B runs) ----
        for (int i = tid; i < CK * 9 * 64; i += 256) {
            int oc  = i / 36;
            int rem = i - oc * 36;
            int c_l = rem / 9;
            int k   = rem - c_l * 9;
            s_w[c_l][k][oc] = wsrc[(size_t)oc * (CIN * 9) + (size_t)(c0 + c_l) * 9 + k];
        }
        __syncthreads();

        // ---- accumulate ----
        for (int c_l = 0; c_l < CK; c_l++) {
            for (int dy = 0; dy < 3; dy++) {
                float rv[8][3];
                #pragma unroll
                for (int i = 0; i < 8; i++)
                    #pragma unroll
                    for (int kx = 0; kx < 3; kx++)
                        rv[i][kx] = s_in[c_l][dy][pxg + 32 * i + kx];
                #pragma unroll
                for (int kx = 0; kx < 3; kx++)
                    #pragma unroll
                    for (int o = 0; o < 8; o++) {
                        float wv = s_w[c_l][dy * 3 + kx][chg * 8 + o];
                        #pragma unroll
                        for (int i = 0; i < 8; i++)
                            acc[o][i] += wv * rv[i][kx];
                    }
            }
        }
        __syncthreads();
    }

    // ---- epilogue: bias + BN fold, write f ----
    const float* bsrc  = half ? bbv : ba;
    const float* gsrc  = half ? gB  : gA;
    const float* besrc = half ? beB : beA;
    const float* msrc  = half ? mB  : mA;
    const float* vsrc  = half ? vB  : vA;
    #pragma unroll
    for (int o = 0; o < 8; o++) {
        int lb = chg * 8 + o;                       // branch-local channel
        float bias = bsrc[lb];
        float sc   = gsrc[lb] * rsqrtf(vsrc[lb] + 1e-3f);
        float sh   = besrc[lb] - msrc[lb] * sc;
        float* fout = g_f + (((size_t)bb * 128 + half * BR + lb) * Hc + y) * Wc;
        #pragma unroll
        for (int i = 0; i < 8; i++)
            fout[pxg + 32 * i] = (acc[o][i] + bias) * sc + sh;
    }
}

// ============================================================================
// Kernel 2: 1x1 attention conv over [f(64), gh, gw] + BN  ->  g_att
// ============================================================================
__global__ void att_kernel(const float* __restrict__ aw, const float* __restrict__ abv,
                           const float* __restrict__ bw, const float* __restrict__ bbv,
                           const float* __restrict__ gA1, const float* __restrict__ beA1,
                           const float* __restrict__ mA1, const float* __restrict__ vA1,
                           const float* __restrict__ gB1, const float* __restrict__ beB1,
                           const float* __restrict__ mB1, const float* __restrict__ vB1,
                           int B)
{
    int idx = blockIdx.x * blockDim.x + threadIdx.x;
    int total = B * HWC;
    if (idx >= total) return;
    int bb  = idx / HWC;
    int pix = idx - bb * HWC;
    int y = pix / Wc;
    int xx = pix - y * Wc;

    const float* f0 = g_f + (size_t)bb * 128 * HWC + pix;
    float sa = 0.f, sb = 0.f;
    #pragma unroll 8
    for (int c = 0; c < 64; c++) {
        sa += __ldg(aw + c) * f0[(size_t)c * HWC];
        sb += __ldg(bw + c) * f0[(size_t)(c + 64) * HWC];
    }
    float ghv = axis_g(y, Hc);
    float gwv = axis_g(xx, Wc);
    sa += __ldg(aw + 64) * ghv + __ldg(aw + 65) * gwv + __ldg(abv);
    sb += __ldg(bw + 64) * ghv + __ldg(bw + 65) * gwv + __ldg(bbv);

    float scA = __ldg(gA1) * rsqrtf(__ldg(vA1) + 1e-5f);
    float scB = __ldg(gB1) * rsqrtf(__ldg(vB1) + 1e-5f);
    sa = (sa - __ldg(mA1)) * scA + __ldg(beA1);
    sb = (sb - __ldg(mB1)) * scB + __ldg(beB1);

    g_att[((size_t)bb * 2 + 0) * HWC + pix] = sa;
    g_att[((size_t)bb * 2 + 1) * HWC + pix] = sb;
}

// ============================================================================
// Kernel 3: 3x3 map conv over [att, gh, gw, pr] -> sigmoid -> scale -> out
// ============================================================================
__global__ void map_out_kernel(const float* __restrict__ wA, const float* __restrict__ wB,
                               const float* __restrict__ s1p, const float* __restrict__ s2p,
                               float* __restrict__ out, int B)
{
    int idx = blockIdx.x * blockDim.x + threadIdx.x;
    int total = B * HWC;
    if (idx >= total) return;
    int bb  = idx / HWC;
    int pix = idx - bb * HWC;
    int y = pix / Wc;
    int x = pix - y * Wc;

    // pr normalization constants (match _linear_map over the full grid)
    float ghmin = ((Hc & 1) == 0) ? 0.5f / (float)(Hc / 2) : 0.f;
    float gwmin = ((Wc & 1) == 0) ? 0.5f / (float)(Wc / 2) : 0.f;
    float ghmax = axis_g(0, Hc);
    float gwmax = axis_g(0, Wc);
    float prmin = sqrtf(ghmin * ghmin + gwmin * gwmin);
    float prmax = sqrtf(ghmax * ghmax + gwmax * gwmax);
    float kk = 2.f / (prmax - prmin);
    float cc = 1.f - prmax * kk;

    float maps[2];
    #pragma unroll
    for (int br = 0; br < 2; br++) {
        const float* w = br ? wB : wA;
        const float* ab = g_att + ((size_t)bb * 2 + br) * HWC;
        float s = 0.f;
        #pragma unroll
        for (int dy = -1; dy <= 1; dy++) {
            int yy = y + dy;
            if (yy < 0 || yy >= Hc) continue;
            float ghv = axis_g(yy, Hc);
            #pragma unroll
            for (int dx = -1; dx <= 1; dx++) {
                int xn = x + dx;
                if (xn < 0 || xn >= Wc) continue;     // zero padding of ALL channels
                float av  = ab[yy * Wc + xn];
                float gwv = axis_g(xn, Wc);
                float pr  = sqrtf(ghv * ghv + gwv * gwv);
                float prn = kk * pr + cc;
                int k = (dy + 1) * 3 + (dx + 1);
                s += __ldg(w + k)      * av
                   + __ldg(w + 9 + k)  * ghv
                   + __ldg(w + 18 + k) * gwv
                   + __ldg(w + 27 + k) * prn;
            }
        }
        float m = 1.f / (1.f + expf(-s));
        maps[br] = m * (br ? __ldg(s2p) : __ldg(s1p));
    }

    const float* f0 = g_f + (size_t)bb * 128 * HWC + pix;
    float*       o0 = out + (size_t)bb * 128 * HWC + pix;
    #pragma unroll 8
    for (int c = 0; c < 128; c++) {
        float m = (c < 64) ? maps[0] : maps[1];
        o0[(size_t)c * HWC] = f0[(size_t)c * HWC] * m;
    }
}

// ============================================================================
extern "C" void kernel_launch(void* const* d_in, const int* in_sizes, int n_in,
                              void* d_out, int out_size)
{
    const float* x        = (const float*)d_in[0];
    const float* conv_a_w = (const float*)d_in[1];
    const float* conv_a_b = (const float*)d_in[2];
    const float* conv_b_w = (const float*)d_in[3];
    const float* conv_b_b = (const float*)d_in[4];
    const float* bn_a_g   = (const float*)d_in[5];
    const float* bn_a_be  = (const float*)d_in[6];
    const float* bn_a_m   = (const float*)d_in[7];
    const float* bn_a_v   = (const float*)d_in[8];
    const float* bn_b_g   = (const float*)d_in[9];
    const float* bn_b_be  = (const float*)d_in[10];
    const float* bn_b_m   = (const float*)d_in[11];
    const float* bn_b_v   = (const float*)d_in[12];
    const float* att_a_w  = (const float*)d_in[13];
    const float* att_a_b  = (const float*)d_in[14];
    const float* att_b_w  = (const float*)d_in[15];
    const float* att_b_b  = (const float*)d_in[16];
    const float* abn_a_g  = (const float*)d_in[17];
    const float* abn_a_be = (const float*)d_in[18];
    const float* abn_a_m  = (const float*)d_in[19];
    const float* abn_a_v  = (const float*)d_in[20];
    const float* abn_b_g  = (const float*)d_in[21];
    const float* abn_b_be = (const float*)d_in[22];
    const float* abn_b_m  = (const float*)d_in[23];
    const float* abn_b_v  = (const float*)d_in[24];
    const float* attn_a_w = (const float*)d_in[25];
    const float* attn_b_w = (const float*)d_in[26];
    const float* scale1   = (const float*)d_in[27];
    const float* scale2   = (const float*)d_in[28];

    int B = in_sizes[0] / (CIN * Hc * Wc);

    dim3 g1(Hc, 2, B);
    conv_bn_kernel<<<g1, 256>>>(x, conv_a_w, conv_a_b, conv_b_w, conv_b_b,
                                bn_a_g, bn_a_be, bn_a_m, bn_a_v,
                                bn_b_g, bn_b_be, bn_b_m, bn_b_v);

    int total = B * HWC;
    int nb = (total + 255) / 256;
    att_kernel<<<nb, 256>>>(att_a_w, att_a_b, att_b_w, att_b_b,
                            abn_a_g, abn_a_be, abn_a_m, abn_a_v,
                            abn_b_g, abn_b_be, abn_b_m, abn_b_v, B);

    map_out_kernel<<<nb, 256>>>(attn_a_w, attn_b_w, scale1, scale2,
                                (float*)d_out, B);
}

// round 4
// speedup vs baseline: 3.3763x; 3.3702x over previous
#include <cuda_runtime.h>
#include <cuda_bf16.h>
#include <math.h>
#include <stdint.h>

#define Hc  256
#define Wc  256
#define CINc 128
#define HWC (Hc * Wc)

// ---------------- scratch (static device globals; no runtime allocation) ----
__device__ float g_f[(size_t)4 * 128 * HWC];                       // post-BN features NCHW
__device__ float g_att[(size_t)4 * 2 * HWC];                       // attention logits
__device__ __align__(256) __nv_bfloat16 g_xhi[(size_t)4 * HWC * 128];  // x hi, NHWC
__device__ __align__(256) __nv_bfloat16 g_xlo[(size_t)4 * HWC * 128];  // x lo, NHWC
__device__ __align__(256) __nv_bfloat16 g_whi[18 * 128 * 64];      // W hi [chunk][oc][k]
__device__ __align__(256) __nv_bfloat16 g_wlo[18 * 128 * 64];      // W lo

// ---------------- helpers ----------------------------------------------------
__device__ __forceinline__ uint32_t smem_u32(const void* p) {
    uint32_t a;
    asm("{ .reg .u64 t; cvta.to.shared.u64 t, %1; cvt.u32.u64 %0, t; }" : "=r"(a) : "l"(p));
    return a;
}
__device__ __forceinline__ void cp16(uint32_t dst, const void* src, uint32_t sz) {
    asm volatile("cp.async.cg.shared.global [%0], [%1], 16, %2;"
                 :: "r"(dst), "l"(src), "r"(sz));
}
#define CP_COMMIT() asm volatile("cp.async.commit_group;" ::: "memory")
#define CP_WAIT1()  asm volatile("cp.async.wait_group 1;" ::: "memory")

__device__ __forceinline__ void ldsm_x4(uint32_t* r, uint32_t a) {
    asm volatile("ldmatrix.sync.aligned.m8n8.x4.shared.b16 {%0,%1,%2,%3}, [%4];"
                 : "=r"(r[0]), "=r"(r[1]), "=r"(r[2]), "=r"(r[3]) : "r"(a));
}
__device__ __forceinline__ void mma16816(float* d, const uint32_t* a, const uint32_t* b) {
    asm volatile("mma.sync.aligned.m16n8k16.row.col.f32.bf16.bf16.f32 "
                 "{%0,%1,%2,%3},{%4,%5,%6,%7},{%8,%9},{%0,%1,%2,%3};"
                 : "+f"(d[0]), "+f"(d[1]), "+f"(d[2]), "+f"(d[3])
                 : "r"(a[0]), "r"(a[1]), "r"(a[2]), "r"(a[3]), "r"(b[0]), "r"(b[1]));
}

// position helper (matches reference)
__device__ __forceinline__ float axis_g(int i, int n) {
    float off = ((n & 1) == 0) ? 0.5f : 0.0f;
    return fabsf((float)i - (float)(n / 2) + off) / (float)(n / 2);
}

// ============================================================================
// prep_x: NCHW fp32 -> NHWC bf16 hi/lo (smem transpose, coalesced both sides)
// ============================================================================
__global__ __launch_bounds__(256)
void prep_x_kernel(const float* __restrict__ x)
{
    __shared__ __nv_bfloat16 s_hi[64 * 136];
    __shared__ __nv_bfloat16 s_lo[64 * 136];
    int blk = blockIdx.x;
    int bb  = blk >> 10;
    int px0 = (blk & 1023) * 64;
    int tid = threadIdx.x;
    int p = tid & 63, cq = tid >> 6;

    const float* xb = x + (size_t)bb * CINc * HWC;
    for (int c0 = 0; c0 < CINc; c0 += 4) {
        int c = c0 + cq;
        float f = xb[(size_t)c * HWC + px0 + p];
        __nv_bfloat16 h = __float2bfloat16(f);
        __nv_bfloat16 l = __float2bfloat16(f - __bfloat162float(h));
        s_hi[p * 136 + c] = h;
        s_lo[p * 136 + c] = l;
    }
    __syncthreads();
    for (int i = tid; i < 64 * 16; i += 256) {
        int p2 = i >> 4, j = i & 15;
        uint4 vh = *(const uint4*)&s_hi[p2 * 136 + j * 8];
        uint4 vl = *(const uint4*)&s_lo[p2 * 136 + j * 8];
        size_t e = ((size_t)bb * HWC + px0 + p2) * 128 + j * 8;
        *(uint4*)(g_xhi + e) = vh;
        *(uint4*)(g_xlo + e) = vl;
    }
}

// ============================================================================
// prep_w: fp32 weights -> g_whi/lo [chunk18][128oc][64k], chunk = (tap, cin-half)
// ============================================================================
__global__ void prep_w_kernel(const float* __restrict__ wa, const float* __restrict__ wb)
{
    int idx = blockIdx.x * 256 + threadIdx.x;
    if (idx >= 18 * 128 * 64) return;
    int k  = idx & 63;
    int oc = (idx >> 6) & 127;
    int c  = idx >> 13;
    int t  = c >> 1, hf = c & 1;
    int cin = hf * 64 + k;
    float w = (oc < 64) ? wa[((size_t)oc * CINc + cin) * 9 + t]
                        : wb[((size_t)(oc - 64) * CINc + cin) * 9 + t];
    __nv_bfloat16 h = __float2bfloat16(w);
    __nv_bfloat16 l = __float2bfloat16(w - __bfloat162float(h));
    g_whi[idx] = h;
    g_wlo[idx] = l;
}

// ============================================================================
// conv_mma: implicit GEMM via mma.sync bf16 (3-term hi/lo split, fp32 accum)
//   CTA: 128 oc x 128 px of one output row; 8 warps, warp tile 32x64
//   K: 18 chunks of 64 (tap x cin-half); cp.async 2-stage pipeline
// ============================================================================
#define A_HI 0
#define A_LO 16384
#define B_HI 32768
#define B_LO 49152
#define STAGE 65536
#define SMEM_TOT (2 * STAGE)

// swizzled 16B offset inside a [row][64k] bf16 tile (row stride 128B)
__device__ __forceinline__ uint32_t swz(int row, int j16) {
    return (uint32_t)(row * 128 + ((j16 ^ (row & 7)) << 4));
}

__global__ __launch_bounds__(256, 1)
void conv_mma_kernel(const float* __restrict__ ba,  const float* __restrict__ bbv,
                     const float* __restrict__ gA,  const float* __restrict__ beA,
                     const float* __restrict__ mA,  const float* __restrict__ vA,
                     const float* __restrict__ gB,  const float* __restrict__ beB,
                     const float* __restrict__ mB,  const float* __restrict__ vB)
{
    extern __shared__ char smem[];
    const uint32_t sb = smem_u32(smem);
    const int tid  = threadIdx.x;
    const int wid  = tid >> 5, lane = tid & 31;
    const int bb   = blockIdx.x >> 9;
    const int y    = (blockIdx.x >> 1) & 255;
    const int pxh  = blockIdx.x & 1;          // which 128-px half of the row
    const int m0   = (wid >> 1) * 32;         // warp oc base
    const int n0   = (wid & 1) * 64;          // warp px base (within 128)

    float C[2][8][4];
    #pragma unroll
    for (int mt = 0; mt < 2; mt++)
        #pragma unroll
        for (int nt = 0; nt < 8; nt++)
            #pragma unroll
            for (int q = 0; q < 4; q++) C[mt][nt][q] = 0.f;

    // ---- chunk loader: issues cp.async into stage buffer, one commit ----
    auto load_chunk = [&](int c, uint32_t stg) {
        int t  = c >> 1, hf = c & 1;
        int yy = y + t / 3 - 1;
        int dx = t % 3 - 1;
        bool vy = (yy >= 0) && (yy < Hc);
        size_t arow = (size_t)c * 8192;                       // A chunk base (elems)
        size_t brow = ((size_t)(bb * Hc + yy) * Wc) * 128;    // B row base (elems)
        #pragma unroll
        for (int i = 0; i < 4; i++) {
            int idx = tid + i * 256;
            int row = idx >> 3, j = idx & 7;
            // A (weights)
            cp16(stg + A_HI + swz(row, j), g_whi + arow + idx * 8, 16);
            cp16(stg + A_LO + swz(row, j), g_wlo + arow + idx * 8, 16);
            // B (im2col X)
            int xx = pxh * 128 + row + dx;
            bool ok = vy && (xx >= 0) && (xx < Wc);
            size_t e = ok ? (brow + (size_t)xx * 128 + hf * 64 + j * 8) : 0;
            uint32_t sz = ok ? 16u : 0u;
            cp16(stg + B_HI + swz(row, j), g_xhi + e, sz);
            cp16(stg + B_LO + swz(row, j), g_xlo + e, sz);
        }
        CP_COMMIT();
    };

    // prologue: prefetch chunks 0 and 1
    load_chunk(0, sb);
    load_chunk(1, sb + STAGE);

    for (int c = 0; c < 18; c++) {
        CP_WAIT1();
        __syncthreads();
        const uint32_t stg = sb + (c & 1) * STAGE;

        #pragma unroll
        for (int kg = 0; kg < 4; kg++) {
            // A fragments (2 m-tiles x {hi,lo})
            uint32_t ah[2][4], al[2][4];
            #pragma unroll
            for (int mt = 0; mt < 2; mt++) {
                int row = m0 + mt * 16 + (lane & 15);
                int kc  = kg * 2 + (lane >> 4);
                uint32_t off = swz(row, kc);
                ldsm_x4(ah[mt], stg + A_HI + off);
                ldsm_x4(al[mt], stg + A_LO + off);
            }
            // B fragments (4 n16-quads x {hi,lo}); each x4 = two n8 frags
            uint32_t bh[4][4], bl[4][4];
            #pragma unroll
            for (int nq = 0; nq < 4; nq++) {
                int row = n0 + nq * 16 + (lane & 7) + ((lane >> 4) << 3);
                int kc  = kg * 2 + ((lane >> 3) & 1);
                uint32_t off = swz(row, kc);
                ldsm_x4(bh[nq], stg + B_HI + off);
                ldsm_x4(bl[nq], stg + B_LO + off);
            }
            #pragma unroll
            for (int mt = 0; mt < 2; mt++)
                #pragma unroll
                for (int nq = 0; nq < 4; nq++)
                    #pragma unroll
                    for (int h = 0; h < 2; h++) {
                        float* acc = C[mt][nq * 2 + h];
                        mma16816(acc, ah[mt], &bh[nq][h * 2]);   // Wh * Xh
                        mma16816(acc, al[mt], &bh[nq][h * 2]);   // Wl * Xh
                        mma16816(acc, ah[mt], &bl[nq][h * 2]);   // Wh * Xl
                    }
        }
        __syncthreads();
        if (c + 2 < 18) load_chunk(c + 2, stg);
        else            CP_COMMIT();      // empty group keeps wait accounting uniform
    }

    // ---- epilogue: BN(+bias) fold, write g_f ----
    #pragma unroll
    for (int mt = 0; mt < 2; mt++) {
        int r0 = m0 + mt * 16 + (lane >> 2);
        #pragma unroll
        for (int hrow = 0; hrow < 2; hrow++) {
            int oc = r0 + hrow * 8;
            float sc, sh;
            if (oc < 64) {
                sc = gA[oc] * rsqrtf(vA[oc] + 1e-3f);
                sh = beA[oc] - mA[oc] * sc + ba[oc] * sc;
            } else {
                int o = oc - 64;
                sc = gB[o] * rsqrtf(vB[o] + 1e-3f);
                sh = beB[o] - mB[o] * sc + bbv[o] * sc;
            }
            float* fout = g_f + (((size_t)bb * 128 + oc) * Hc + y) * Wc + pxh * 128;
            #pragma unroll
            for (int nt = 0; nt < 8; nt++) {
                int col = n0 + nt * 8 + 2 * (lane & 3);
                float2 v;
                v.x = C[mt][nt][hrow * 2 + 0] * sc + sh;
                v.y = C[mt][nt][hrow * 2 + 1] * sc + sh;
                *(float2*)(fout + col) = v;
            }
        }
    }
}

// ============================================================================
// att: 1x1 attention conv over [f(64), gh, gw] + BN  -> g_att
// ============================================================================
__global__ void att_kernel(const float* __restrict__ aw, const float* __restrict__ abv,
                           const float* __restrict__ bw, const float* __restrict__ bbv,
                           const float* __restrict__ gA1, const float* __restrict__ beA1,
                           const float* __restrict__ mA1, const float* __restrict__ vA1,
                           const float* __restrict__ gB1, const float* __restrict__ beB1,
                           const float* __restrict__ mB1, const float* __restrict__ vB1,
                           int B)
{
    int idx = blockIdx.x * blockDim.x + threadIdx.x;
    int total = B * HWC;
    if (idx >= total) return;
    int bb  = idx / HWC;
    int pix = idx - bb * HWC;
    int y = pix / Wc;
    int xx = pix - y * Wc;

    const float* f0 = g_f + (size_t)bb * 128 * HWC + pix;
    float sa = 0.f, sb2 = 0.f;
    #pragma unroll 8
    for (int c = 0; c < 64; c++) {
        sa  += __ldg(aw + c) * f0[(size_t)c * HWC];
        sb2 += __ldg(bw + c) * f0[(size_t)(c + 64) * HWC];
    }
    float ghv = axis_g(y, Hc);
    float gwv = axis_g(xx, Wc);
    sa  += __ldg(aw + 64) * ghv + __ldg(aw + 65) * gwv + __ldg(abv);
    sb2 += __ldg(bw + 64) * ghv + __ldg(bw + 65) * gwv + __ldg(bbv);

    float scA = __ldg(gA1) * rsqrtf(__ldg(vA1) + 1e-5f);
    float scB = __ldg(gB1) * rsqrtf(__ldg(vB1) + 1e-5f);
    sa  = (sa  - __ldg(mA1)) * scA + __ldg(beA1);
    sb2 = (sb2 - __ldg(mB1)) * scB + __ldg(beB1);

    g_att[((size_t)bb * 2 + 0) * HWC + pix] = sa;
    g_att[((size_t)bb * 2 + 1) * HWC + pix] = sb2;
}

// ============================================================================
// map_out: 3x3 conv over [att, gh, gw, pr] -> sigmoid -> scale -> out
// ============================================================================
__global__ void map_out_kernel(const float* __restrict__ wA, const float* __restrict__ wB,
                               const float* __restrict__ s1p, const float* __restrict__ s2p,
                               float* __restrict__ out, int B)
{
    int idx = blockIdx.x * blockDim.x + threadIdx.x;
    int total = B * HWC;
    if (idx >= total) return;
    int bb  = idx / HWC;
    int pix = idx - bb * HWC;
    int y = pix / Wc;
    int x = pix - y * Wc;

    float ghmin = 0.5f / (float)(Hc / 2);
    float gwmin = 0.5f / (float)(Wc / 2);
    float ghmax = axis_g(0, Hc);
    float gwmax = axis_g(0, Wc);
    float prmin = sqrtf(ghmin * ghmin + gwmin * gwmin);
    float prmax = sqrtf(ghmax * ghmax + gwmax * gwmax);
    float kk = 2.f / (prmax - prmin);
    float cc = 1.f - prmax * kk;

    float maps[2];
    #pragma unroll
    for (int br = 0; br < 2; br++) {
        const float* w = br ? wB : wA;
        const float* ab = g_att + ((size_t)bb * 2 + br) * HWC;
        float s = 0.f;
        #pragma unroll
        for (int dy = -1; dy <= 1; dy++) {
            int yy = y + dy;
            if (yy < 0 || yy >= Hc) continue;
            float ghv = axis_g(yy, Hc);
            #pragma unroll
            for (int dxx = -1; dxx <= 1; dxx++) {
                int xn = x + dxx;
                if (xn < 0 || xn >= Wc) continue;
                float av  = ab[yy * Wc + xn];
                float gwv = axis_g(xn, Wc);
                float pr  = sqrtf(ghv * ghv + gwv * gwv);
                float prn = kk * pr + cc;
                int k = (dy + 1) * 3 + (dxx + 1);
                s += __ldg(w + k)      * av
                   + __ldg(w + 9 + k)  * ghv
                   + __ldg(w + 18 + k) * gwv
                   + __ldg(w + 27 + k) * prn;
            }
        }
        float m = 1.f / (1.f + expf(-s));
        maps[br] = m * (br ? __ldg(s2p) : __ldg(s1p));
    }

    const float* f0 = g_f + (size_t)bb * 128 * HWC + pix;
    float*       o0 = out + (size_t)bb * 128 * HWC + pix;
    #pragma unroll 8
    for (int c = 0; c < 128; c++) {
        float m = (c < 64) ? maps[0] : maps[1];
        o0[(size_t)c * HWC] = f0[(size_t)c * HWC] * m;
    }
}

// ============================================================================
extern "C" void kernel_launch(void* const* d_in, const int* in_sizes, int n_in,
                              void* d_out, int out_size)
{
    const float* x        = (const float*)d_in[0];
    const float* conv_a_w = (const float*)d_in[1];
    const float* conv_a_b = (const float*)d_in[2];
    const float* conv_b_w = (const float*)d_in[3];
    const float* conv_b_b = (const float*)d_in[4];
    const float* bn_a_g   = (const float*)d_in[5];
    const float* bn_a_be  = (const float*)d_in[6];
    const float* bn_a_m   = (const float*)d_in[7];
    const float* bn_a_v   = (const float*)d_in[8];
    const float* bn_b_g   = (const float*)d_in[9];
    const float* bn_b_be  = (const float*)d_in[10];
    const float* bn_b_m   = (const float*)d_in[11];
    const float* bn_b_v   = (const float*)d_in[12];
    const float* att_a_w  = (const float*)d_in[13];
    const float* att_a_b  = (const float*)d_in[14];
    const float* att_b_w  = (const float*)d_in[15];
    const float* att_b_b  = (const float*)d_in[16];
    const float* abn_a_g  = (const float*)d_in[17];
    const float* abn_a_be = (const float*)d_in[18];
    const float* abn_a_m  = (const float*)d_in[19];
    const float* abn_a_v  = (const float*)d_in[20];
    const float* abn_b_g  = (const float*)d_in[21];
    const float* abn_b_be = (const float*)d_in[22];
    const float* abn_b_m  = (const float*)d_in[23];
    const float* abn_b_v  = (const float*)d_in[24];
    const float* attn_a_w = (const float*)d_in[25];
    const float* attn_b_w = (const float*)d_in[26];
    const float* scale1   = (const float*)d_in[27];
    const float* scale2   = (const float*)d_in[28];

    int B = in_sizes[0] / (CINc * HWC);

    cudaFuncSetAttribute(conv_mma_kernel,
                         cudaFuncAttributeMaxDynamicSharedMemorySize, SMEM_TOT);

    prep_x_kernel<<<B * 1024, 256>>>(x);
    prep_w_kernel<<<(18 * 128 * 64 + 255) / 256, 256>>>(conv_a_w, conv_b_w);

    conv_mma_kernel<<<B * 512, 256, SMEM_TOT>>>(
        conv_a_b, conv_b_b,
        bn_a_g, bn_a_be, bn_a_m, bn_a_v,
        bn_b_g, bn_b_be, bn_b_m, bn_b_v);

    int total = B * HWC;
    int nb = (total + 255) / 256;
    att_kernel<<<nb, 256>>>(att_a_w, att_a_b, att_b_w, att_b_b,
                            abn_a_g, abn_a_be, abn_a_m, abn_a_v,
                            abn_b_g, abn_b_be, abn_b_m, abn_b_v, B);

    map_out_kernel<<<nb, 256>>>(attn_a_w, attn_b_w, scale1, scale2,
                                (float*)d_out, B);
}

// round 5
// speedup vs baseline: 4.4461x; 1.3169x over previous
#include <cuda_runtime.h>
#include <cuda_fp16.h>
#include <math.h>
#include <stdint.h>

#define Hc  256
#define Wc  256
#define CINc 128
#define HWC (Hc * Wc)

// ---------------- scratch (static device globals; no runtime allocation) ----
__device__ float g_f[(size_t)4 * 128 * HWC];                   // post-BN features NCHW
__device__ float g_att[(size_t)4 * 2 * HWC];                   // attention logits
__device__ __align__(256) __half g_xh[(size_t)4 * HWC * 128];  // x fp16, NHWC
__device__ __align__(256) __half g_whi[18 * 128 * 64];         // (W*16) hi [chunk][oc][k]
__device__ __align__(256) __half g_wlo[18 * 128 * 64];         // (W*16) lo

// ---------------- helpers ----------------------------------------------------
__device__ __forceinline__ uint32_t smem_u32(const void* p) {
    uint32_t a;
    asm("{ .reg .u64 t; cvta.to.shared.u64 t, %1; cvt.u32.u64 %0, t; }" : "=r"(a) : "l"(p));
    return a;
}
__device__ __forceinline__ void cp16(uint32_t dst, const void* src, uint32_t sz) {
    asm volatile("cp.async.cg.shared.global [%0], [%1], 16, %2;"
                 :: "r"(dst), "l"(src), "r"(sz));
}
#define CP_COMMIT() asm volatile("cp.async.commit_group;" ::: "memory")
#define CP_WAIT2()  asm volatile("cp.async.wait_group 2;" ::: "memory")

__device__ __forceinline__ void ldsm_x4(uint32_t* r, uint32_t a) {
    asm volatile("ldmatrix.sync.aligned.m8n8.x4.shared.b16 {%0,%1,%2,%3}, [%4];"
                 : "=r"(r[0]), "=r"(r[1]), "=r"(r[2]), "=r"(r[3]) : "r"(a));
}
__device__ __forceinline__ void mma16816(float* d, const uint32_t* a, const uint32_t* b) {
    asm volatile("mma.sync.aligned.m16n8k16.row.col.f32.f16.f16.f32 "
                 "{%0,%1,%2,%3},{%4,%5,%6,%7},{%8,%9},{%0,%1,%2,%3};"
                 : "+f"(d[0]), "+f"(d[1]), "+f"(d[2]), "+f"(d[3])
                 : "r"(a[0]), "r"(a[1]), "r"(a[2]), "r"(a[3]), "r"(b[0]), "r"(b[1]));
}

// position helper (matches reference)
__device__ __forceinline__ float axis_g(int i, int n) {
    float off = ((n & 1) == 0) ? 0.5f : 0.0f;
    return fabsf((float)i - (float)(n / 2) + off) / (float)(n / 2);
}

// ============================================================================
// prep_x: NCHW fp32 -> NHWC fp16 (smem transpose, coalesced both sides)
// ============================================================================
__global__ __launch_bounds__(256)
void prep_x_kernel(const float* __restrict__ x)
{
    __shared__ __half s_h[64 * 136];
    int blk = blockIdx.x;
    int bb  = blk >> 10;
    int px0 = (blk & 1023) * 64;
    int tid = threadIdx.x;
    int p = tid & 63, cq = tid >> 6;

    const float* xb = x + (size_t)bb * CINc * HWC;
    for (int c0 = 0; c0 < CINc; c0 += 4) {
        int c = c0 + cq;
        s_h[p * 136 + c] = __float2half(xb[(size_t)c * HWC + px0 + p]);
    }
    __syncthreads();
    for (int i = tid; i < 64 * 16; i += 256) {
        int p2 = i >> 4, j = i & 15;
        uint4 v = *(const uint4*)&s_h[p2 * 136 + j * 8];
        size_t e = ((size_t)bb * HWC + px0 + p2) * 128 + j * 8;
        *(uint4*)(g_xh + e) = v;
    }
}

// ============================================================================
// prep_w: fp32 weights *16 -> fp16 hi/lo, [chunk18][128oc][64k]
// ============================================================================
__global__ void prep_w_kernel(const float* __restrict__ wa, const float* __restrict__ wb)
{
    int idx = blockIdx.x * 256 + threadIdx.x;
    if (idx >= 18 * 128 * 64) return;
    int k  = idx & 63;
    int oc = (idx >> 6) & 127;
    int c  = idx >> 13;
    int t  = c >> 1, hf = c & 1;
    int cin = hf * 64 + k;
    float w = (oc < 64) ? wa[((size_t)oc * CINc + cin) * 9 + t]
                        : wb[((size_t)(oc - 64) * CINc + cin) * 9 + t];
    w *= 16.0f;                              // keep W-lo normal in fp16
    __half h = __float2half(w);
    __half l = __float2half(w - __half2float(h));
    g_whi[idx] = h;
    g_wlo[idx] = l;
}

// ============================================================================
// conv_mma: implicit GEMM via mma.sync fp16 (2-term W hi/lo split, fp32 accum)
//   CTA: 128 oc x 128 px of one output row; 8 warps, warp tile 32x64
//   K: 18 chunks of 64 (tap x cin-half); cp.async 3-stage pipeline
// ============================================================================
#define A_HI 0
#define A_LO 16384
#define B_X  32768
#define STAGE 49152
#define SMEM_TOT (3 * STAGE)

// swizzled 16B offset inside a [row][64k] fp16 tile (row stride 128B)
__device__ __forceinline__ uint32_t swz(int row, int j16) {
    return (uint32_t)(row * 128 + ((j16 ^ (row & 7)) << 4));
}

__global__ __launch_bounds__(256, 1)
void conv_mma_kernel(const float* __restrict__ ba,  const float* __restrict__ bbv,
                     const float* __restrict__ gA,  const float* __restrict__ beA,
                     const float* __restrict__ mA,  const float* __restrict__ vA,
                     const float* __restrict__ gB,  const float* __restrict__ beB,
                     const float* __restrict__ mB,  const float* __restrict__ vB)
{
    extern __shared__ char smem[];
    const uint32_t sb = smem_u32(smem);
    const int tid  = threadIdx.x;
    const int wid  = tid >> 5, lane = tid & 31;
    const int bb   = blockIdx.x >> 9;
    const int y    = (blockIdx.x >> 1) & 255;
    const int pxh  = blockIdx.x & 1;          // which 128-px half of the row
    const int m0   = (wid >> 1) * 32;         // warp oc base
    const int n0   = (wid & 1) * 64;          // warp px base (within 128)

    float C[2][8][4];
    #pragma unroll
    for (int mt = 0; mt < 2; mt++)
        #pragma unroll
        for (int nt = 0; nt < 8; nt++)
            #pragma unroll
            for (int q = 0; q < 4; q++) C[mt][nt][q] = 0.f;

    // ---- chunk loader: cp.async into stage, one commit ----
    auto load_chunk = [&](int c) {
        uint32_t stg = sb + (uint32_t)(c % 3) * STAGE;
        int t  = c >> 1, hf = c & 1;
        int yy = y + t / 3 - 1;
        int dx = t % 3 - 1;
        bool vy = (yy >= 0) && (yy < Hc);
        size_t arow = (size_t)c * 8192;                       // A chunk base (elems)
        size_t brow = ((size_t)(bb * Hc + yy) * Wc) * 128;    // B row base (elems)
        #pragma unroll
        for (int i = 0; i < 4; i++) {
            int idx = tid + i * 256;
            int row = idx >> 3, j = idx & 7;
            // A (weights hi + lo)
            cp16(stg + A_HI + swz(row, j), g_whi + arow + idx * 8, 16);
            cp16(stg + A_LO + swz(row, j), g_wlo + arow + idx * 8, 16);
            // B (im2col X)
            int xx = pxh * 128 + row + dx;
            bool ok = vy && (xx >= 0) && (xx < Wc);
            size_t e = ok ? (brow + (size_t)xx * 128 + hf * 64 + j * 8) : 0;
            cp16(stg + B_X + swz(row, j), g_xh + e, ok ? 16u : 0u);
        }
        CP_COMMIT();
    };

    // prologue: prefetch chunks 0..2
    load_chunk(0);
    load_chunk(1);
    load_chunk(2);

    for (int c = 0; c < 18; c++) {
        CP_WAIT2();                  // chunk c arrived (≤2 newer groups in flight)
        __syncthreads();
        const uint32_t stg = sb + (uint32_t)(c % 3) * STAGE;

        #pragma unroll
        for (int kg = 0; kg < 4; kg++) {
            uint32_t ah[2][4], al[2][4];
            #pragma unroll
            for (int mt = 0; mt < 2; mt++) {
                int row = m0 + mt * 16 + (lane & 15);
                int kc  = kg * 2 + (lane >> 4);
                uint32_t off = swz(row, kc);
                ldsm_x4(ah[mt], stg + A_HI + off);
                ldsm_x4(al[mt], stg + A_LO + off);
            }
            uint32_t bx[4][4];
            #pragma unroll
            for (int nq = 0; nq < 4; nq++) {
                int row = n0 + nq * 16 + (lane & 7) + ((lane >> 4) << 3);
                int kc  = kg * 2 + ((lane >> 3) & 1);
                ldsm_x4(bx[nq], stg + B_X + swz(row, kc));
            }
            #pragma unroll
            for (int mt = 0; mt < 2; mt++)
                #pragma unroll
                for (int nq = 0; nq < 4; nq++)
                    #pragma unroll
                    for (int h = 0; h < 2; h++) {
                        float* acc = C[mt][nq * 2 + h];
                        mma16816(acc, ah[mt], &bx[nq][h * 2]);   // Wh * X
                        mma16816(acc, al[mt], &bx[nq][h * 2]);   // Wl * X
                    }
        }
        __syncthreads();
        if (c + 3 < 18) load_chunk(c + 3);   // overlaps MMA of c+1, c+2
        else            CP_COMMIT();         // uniform group accounting
    }

    // ---- epilogue: undo W*16 scale, BN(+bias) fold, write g_f ----
    #pragma unroll
    for (int mt = 0; mt < 2; mt++) {
        int r0 = m0 + mt * 16 + (lane >> 2);
        #pragma unroll
        for (int hrow = 0; hrow < 2; hrow++) {
            int oc = r0 + hrow * 8;
            float sc, sh;
            if (oc < 64) {
                sc = gA[oc] * rsqrtf(vA[oc] + 1e-3f);
                sh = beA[oc] - mA[oc] * sc + ba[oc] * sc;
            } else {
                int o = oc - 64;
                sc = gB[o] * rsqrtf(vB[o] + 1e-3f);
                sh = beB[o] - mB[o] * sc + bbv[o] * sc;
            }
            float scq = sc * (1.0f / 16.0f);
            float* fout = g_f + (((size_t)bb * 128 + oc) * Hc + y) * Wc + pxh * 128;
            #pragma unroll
            for (int nt = 0; nt < 8; nt++) {
                int col = n0 + nt * 8 + 2 * (lane & 3);
                float2 v;
                v.x = C[mt][nt][hrow * 2 + 0] * scq + sh;
                v.y = C[mt][nt][hrow * 2 + 1] * scq + sh;
                *(float2*)(fout + col) = v;
            }
        }
    }
}

// ============================================================================
// att: 1x1 attention conv over [f(64), gh, gw] + BN  -> g_att
// ============================================================================
__global__ void att_kernel(const float* __restrict__ aw, const float* __restrict__ abv,
                           const float* __restrict__ bw, const float* __restrict__ bbv,
                           const float* __restrict__ gA1, const float* __restrict__ beA1,
                           const float* __restrict__ mA1, const float* __restrict__ vA1,
                           const float* __restrict__ gB1, const float* __restrict__ beB1,
                           const float* __restrict__ mB1, const float* __restrict__ vB1,
                           int B)
{
    int idx = blockIdx.x * blockDim.x + threadIdx.x;
    int total = B * HWC;
    if (idx >= total) return;
    int bb  = idx / HWC;
    int pix = idx - bb * HWC;
    int y = pix / Wc;
    int xx = pix - y * Wc;

    const float* f0 = g_f + (size_t)bb * 128 * HWC + pix;
    float sa = 0.f, sb2 = 0.f;
    #pragma unroll 8
    for (int c = 0; c < 64; c++) {
        sa  += __ldg(aw + c) * f0[(size_t)c * HWC];
        sb2 += __ldg(bw + c) * f0[(size_t)(c + 64) * HWC];
    }
    float ghv = axis_g(y, Hc);
    float gwv = axis_g(xx, Wc);
    sa  += __ldg(aw + 64) * ghv + __ldg(aw + 65) * gwv + __ldg(abv);
    sb2 += __ldg(bw + 64) * ghv + __ldg(bw + 65) * gwv + __ldg(bbv);

    float scA = __ldg(gA1) * rsqrtf(__ldg(vA1) + 1e-5f);
    float scB = __ldg(gB1) * rsqrtf(__ldg(vB1) + 1e-5f);
    sa  = (sa  - __ldg(mA1)) * scA + __ldg(beA1);
    sb2 = (sb2 - __ldg(mB1)) * scB + __ldg(beB1);

    g_att[((size_t)bb * 2 + 0) * HWC + pix] = sa;
    g_att[((size_t)bb * 2 + 1) * HWC + pix] = sb2;
}

// ============================================================================
// map_out: 3x3 conv over [att, gh, gw, pr] -> sigmoid -> scale -> out
// ============================================================================
__global__ void map_out_kernel(const float* __restrict__ wA, const float* __restrict__ wB,
                               const float* __restrict__ s1p, const float* __restrict__ s2p,
                               float* __restrict__ out, int B)
{
    int idx = blockIdx.x * blockDim.x + threadIdx.x;
    int total = B * HWC;
    if (idx >= total) return;
    int bb  = idx / HWC;
    int pix = idx - bb * HWC;
    int y = pix / Wc;
    int x = pix - y * Wc;

    float ghmin = 0.5f / (float)(Hc / 2);
    float gwmin = 0.5f / (float)(Wc / 2);
    float ghmax = axis_g(0, Hc);
    float gwmax = axis_g(0, Wc);
    float prmin = sqrtf(ghmin * ghmin + gwmin * gwmin);
    float prmax = sqrtf(ghmax * ghmax + gwmax * gwmax);
    float kk = 2.f / (prmax - prmin);
    float cc = 1.f - prmax * kk;

    float maps[2];
    #pragma unroll
    for (int br = 0; br < 2; br++) {
        const float* w = br ? wB : wA;
        const float* ab = g_att + ((size_t)bb * 2 + br) * HWC;
        float s = 0.f;
        #pragma unroll
        for (int dy = -1; dy <= 1; dy++) {
            int yy = y + dy;
            if (yy < 0 || yy >= Hc) continue;
            float ghv = axis_g(yy, Hc);
            #pragma unroll
            for (int dxx = -1; dxx <= 1; dxx++) {
                int xn = x + dxx;
                if (xn < 0 || xn >= Wc) continue;
                float av  = ab[yy * Wc + xn];
                float gwv = axis_g(xn, Wc);
                float pr  = sqrtf(ghv * ghv + gwv * gwv);
                float prn = kk * pr + cc;
                int k = (dy + 1) * 3 + (dxx + 1);
                s += __ldg(w + k)      * av
                   + __ldg(w + 9 + k)  * ghv
                   + __ldg(w + 18 + k) * gwv
                   + __ldg(w + 27 + k) * prn;
            }
        }
        float m = 1.f / (1.f + expf(-s));
        maps[br] = m * (br ? __ldg(s2p) : __ldg(s1p));
    }

    const float* f0 = g_f + (size_t)bb * 128 * HWC + pix;
    float*       o0 = out + (size_t)bb * 128 * HWC + pix;
    #pragma unroll 8
    for (int c = 0; c < 128; c++) {
        float m = (c < 64) ? maps[0] : maps[1];
        o0[(size_t)c * HWC] = f0[(size_t)c * HWC] * m;
    }
}

// ============================================================================
extern "C" void kernel_launch(void* const* d_in, const int* in_sizes, int n_in,
                              void* d_out, int out_size)
{
    const float* x        = (const float*)d_in[0];
    const float* conv_a_w = (const float*)d_in[1];
    const float* conv_a_b = (const float*)d_in[2];
    const float* conv_b_w = (const float*)d_in[3];
    const float* conv_b_b = (const float*)d_in[4];
    const float* bn_a_g   = (const float*)d_in[5];
    const float* bn_a_be  = (const float*)d_in[6];
    const float* bn_a_m   = (const float*)d_in[7];
    const float* bn_a_v   = (const float*)d_in[8];
    const float* bn_b_g   = (const float*)d_in[9];
    const float* bn_b_be  = (const float*)d_in[10];
    const float* bn_b_m   = (const float*)d_in[11];
    const float* bn_b_v   = (const float*)d_in[12];
    const float* att_a_w  = (const float*)d_in[13];
    const float* att_a_b  = (const float*)d_in[14];
    const float* att_b_w  = (const float*)d_in[15];
    const float* att_b_b  = (const float*)d_in[16];
    const float* abn_a_g  = (const float*)d_in[17];
    const float* abn_a_be = (const float*)d_in[18];
    const float* abn_a_m  = (const float*)d_in[19];
    const float* abn_a_v  = (const float*)d_in[20];
    const float* abn_b_g  = (const float*)d_in[21];
    const float* abn_b_be = (const float*)d_in[22];
    const float* abn_b_m  = (const float*)d_in[23];
    const float* abn_b_v  = (const float*)d_in[24];
    const float* attn_a_w = (const float*)d_in[25];
    const float* attn_b_w = (const float*)d_in[26];
    const float* scale1   = (const float*)d_in[27];
    const float* scale2   = (const float*)d_in[28];

    int B = in_sizes[0] / (CINc * HWC);

    cudaFuncSetAttribute(conv_mma_kernel,
                         cudaFuncAttributeMaxDynamicSharedMemorySize, SMEM_TOT);

    prep_x_kernel<<<B * 1024, 256>>>(x);
    prep_w_kernel<<<(18 * 128 * 64 + 255) / 256, 256>>>(conv_a_w, conv_b_w);

    conv_mma_kernel<<<B * 512, 256, SMEM_TOT>>>(
        conv_a_b, conv_b_b,
        bn_a_g, bn_a_be, bn_a_m, bn_a_v,
        bn_b_g, bn_b_be, bn_b_m, bn_b_v);

    int total = B * HWC;
    int nb = (total + 255) / 256;
    att_kernel<<<nb, 256>>>(att_a_w, att_a_b, att_b_w, att_b_b,
                            abn_a_g, abn_a_be, abn_a_m, abn_a_v,
                            abn_b_g, abn_b_be, abn_b_m, abn_b_v, B);

    map_out_kernel<<<nb, 256>>>(attn_a_w, attn_b_w, scale1, scale2,
                                (float*)d_out, B);
}

// round 6
// speedup vs baseline: 4.9604x; 1.1157x over previous
#include <cuda_runtime.h>
#include <cuda_fp16.h>
#include <math.h>
#include <stdint.h>

#define Hc  256
#define Wc  256
#define CINc 128
#define HWC (Hc * Wc)

// ---------------- scratch (static device globals; no runtime allocation) ----
__device__ float g_f[(size_t)4 * 128 * HWC];                   // post-BN features NCHW
__device__ float g_att[(size_t)4 * 2 * HWC];                   // attention logits
__device__ __align__(256) __half g_xh[(size_t)4 * HWC * 128];  // x fp16, NHWC
__device__ __align__(256) __half g_whi[18 * 128 * 64];         // (W*16) hi [chunk][oc][k]
__device__ __align__(256) __half g_wlo[18 * 128 * 64];         // (W*16) lo

// ---------------- helpers ----------------------------------------------------
__device__ __forceinline__ uint32_t smem_u32(const void* p) {
    uint32_t a;
    asm("{ .reg .u64 t; cvta.to.shared.u64 t, %1; cvt.u32.u64 %0, t; }" : "=r"(a) : "l"(p));
    return a;
}
__device__ __forceinline__ void cp16(uint32_t dst, const void* src, uint32_t sz) {
    asm volatile("cp.async.cg.shared.global [%0], [%1], 16, %2;"
                 :: "r"(dst), "l"(src), "r"(sz));
}
#define CP_COMMIT() asm volatile("cp.async.commit_group;" ::: "memory")
#define CP_WAIT2()  asm volatile("cp.async.wait_group 2;" ::: "memory")

__device__ __forceinline__ void ldsm_x4(uint32_t* r, uint32_t a) {
    asm volatile("ldmatrix.sync.aligned.m8n8.x4.shared.b16 {%0,%1,%2,%3}, [%4];"
                 : "=r"(r[0]), "=r"(r[1]), "=r"(r[2]), "=r"(r[3]) : "r"(a));
}
__device__ __forceinline__ void mma16816(float* d, const uint32_t* a, const uint32_t* b) {
    asm volatile("mma.sync.aligned.m16n8k16.row.col.f32.f16.f16.f32 "
                 "{%0,%1,%2,%3},{%4,%5,%6,%7},{%8,%9},{%0,%1,%2,%3};"
                 : "+f"(d[0]), "+f"(d[1]), "+f"(d[2]), "+f"(d[3])
                 : "r"(a[0]), "r"(a[1]), "r"(a[2]), "r"(a[3]), "r"(b[0]), "r"(b[1]));
}

// position helper (matches reference)
__device__ __forceinline__ float axis_g(int i, int n) {
    float off = ((n & 1) == 0) ? 0.5f : 0.0f;
    return fabsf((float)i - (float)(n / 2) + off) / (float)(n / 2);
}

// ============================================================================
// prep_x: NCHW fp32 -> NHWC fp16 (smem transpose, coalesced both sides)
// ============================================================================
__global__ __launch_bounds__(256)
void prep_x_kernel(const float* __restrict__ x)
{
    __shared__ __half s_h[64 * 136];
    int blk = blockIdx.x;
    int bb  = blk >> 10;
    int px0 = (blk & 1023) * 64;
    int tid = threadIdx.x;
    int p = tid & 63, cq = tid >> 6;

    const float* xb = x + (size_t)bb * CINc * HWC;
    for (int c0 = 0; c0 < CINc; c0 += 4) {
        int c = c0 + cq;
        s_h[p * 136 + c] = __float2half(xb[(size_t)c * HWC + px0 + p]);
    }
    __syncthreads();
    for (int i = tid; i < 64 * 16; i += 256) {
        int p2 = i >> 4, j = i & 15;
        uint4 v = *(const uint4*)&s_h[p2 * 136 + j * 8];
        size_t e = ((size_t)bb * HWC + px0 + p2) * 128 + j * 8;
        *(uint4*)(g_xh + e) = v;
    }
}

// ============================================================================
// prep_w: fp32 weights *16 -> fp16 hi/lo, [chunk18][128oc][64k]
// ============================================================================
__global__ void prep_w_kernel(const float* __restrict__ wa, const float* __restrict__ wb)
{
    int idx = blockIdx.x * 256 + threadIdx.x;
    if (idx >= 18 * 128 * 64) return;
    int k  = idx & 63;
    int oc = (idx >> 6) & 127;
    int c  = idx >> 13;
    int t  = c >> 1, hf = c & 1;
    int cin = hf * 64 + k;
    float w = (oc < 64) ? wa[((size_t)oc * CINc + cin) * 9 + t]
                        : wb[((size_t)(oc - 64) * CINc + cin) * 9 + t];
    w *= 16.0f;                              // keep W-lo normal in fp16
    __half h = __float2half(w);
    __half l = __float2half(w - __half2float(h));
    g_whi[idx] = h;
    g_wlo[idx] = l;
}

// ============================================================================
// conv_mma: implicit GEMM via mma.sync fp16 (2-term W hi/lo split, fp32 accum)
//   CTA: 128 oc x 256 px (one full output row); 8 warps, warp tile 32x128
//   K: 18 chunks of 64 (tap x cin-half); cp.async 3-stage pipeline
//   Epilogue: BN fold -> g_f, PLUS fused 1x1 attention conv -> g_att
// ============================================================================
#define A_HI 0
#define A_LO 16384
#define B_X  32768
#define STAGE 65536
#define SMEM_TOT (3 * STAGE)

// swizzled 16B offset inside a [row][64k] fp16 tile (row stride 128B)
__device__ __forceinline__ uint32_t swz(int row, int j16) {
    return (uint32_t)(row * 128 + ((j16 ^ (row & 7)) << 4));
}

__global__ __launch_bounds__(256, 1)
void conv_mma_kernel(const float* __restrict__ ba,  const float* __restrict__ bbv,
                     const float* __restrict__ gA,  const float* __restrict__ beA,
                     const float* __restrict__ mA,  const float* __restrict__ vA,
                     const float* __restrict__ gB,  const float* __restrict__ beB,
                     const float* __restrict__ mB,  const float* __restrict__ vB,
                     const float* __restrict__ aw,  const float* __restrict__ abv,
                     const float* __restrict__ bw,  const float* __restrict__ bb2,
                     const float* __restrict__ gA1, const float* __restrict__ beA1,
                     const float* __restrict__ mA1, const float* __restrict__ vA1,
                     const float* __restrict__ gB1, const float* __restrict__ beB1,
                     const float* __restrict__ mB1, const float* __restrict__ vB1)
{
    extern __shared__ char smem[];
    const uint32_t sb = smem_u32(smem);
    const int tid  = threadIdx.x;
    const int wid  = tid >> 5, lane = tid & 31;
    const int bb   = blockIdx.x >> 8;
    const int y    = blockIdx.x & 255;
    const int m0   = (wid >> 1) * 32;         // warp oc base
    const int n0   = (wid & 1) * 128;         // warp px base

    float C[2][16][4];
    #pragma unroll
    for (int mt = 0; mt < 2; mt++)
        #pragma unroll
        for (int nt = 0; nt < 16; nt++)
            #pragma unroll
            for (int q = 0; q < 4; q++) C[mt][nt][q] = 0.f;

    // ---- chunk loader: cp.async into stage, one commit ----
    auto load_chunk = [&](int c) {
        uint32_t stg = sb + (uint32_t)(c % 3) * STAGE;
        int t  = c >> 1, hf = c & 1;
        int yy = y + t / 3 - 1;
        int dx = t % 3 - 1;
        bool vy = (yy >= 0) && (yy < Hc);
        size_t arow = (size_t)c * 8192;                       // A chunk base (elems)
        size_t brow = ((size_t)(bb * Hc + yy) * Wc) * 128;    // B row base (elems)
        #pragma unroll
        for (int i = 0; i < 4; i++) {                         // A hi+lo: 128 rows
            int idx = tid + i * 256;
            int row = idx >> 3, j = idx & 7;
            cp16(stg + A_HI + swz(row, j), g_whi + arow + idx * 8, 16);
            cp16(stg + A_LO + swz(row, j), g_wlo + arow + idx * 8, 16);
        }
        #pragma unroll
        for (int i = 0; i < 8; i++) {                         // B: 256 px rows
            int idx = tid + i * 256;
            int row = idx >> 3, j = idx & 7;
            int xx = row + dx;
            bool ok = vy && (xx >= 0) && (xx < Wc);
            size_t e = ok ? (brow + (size_t)xx * 128 + hf * 64 + j * 8) : 0;
            cp16(stg + B_X + swz(row, j), g_xh + e, ok ? 16u : 0u);
        }
        CP_COMMIT();
    };

    // prologue: prefetch chunks 0..2
    load_chunk(0);
    load_chunk(1);
    load_chunk(2);

    for (int c = 0; c < 18; c++) {
        CP_WAIT2();
        __syncthreads();
        const uint32_t stg = sb + (uint32_t)(c % 3) * STAGE;

        #pragma unroll
        for (int kg = 0; kg < 4; kg++) {
            uint32_t ah[2][4], al[2][4];
            #pragma unroll
            for (int mt = 0; mt < 2; mt++) {
                int row = m0 + mt * 16 + (lane & 15);
                int kc  = kg * 2 + (lane >> 4);
                uint32_t off = swz(row, kc);
                ldsm_x4(ah[mt], stg + A_HI + off);
                ldsm_x4(al[mt], stg + A_LO + off);
            }
            #pragma unroll
            for (int nq = 0; nq < 8; nq++) {
                uint32_t bx[4];
                int row = n0 + nq * 16 + (lane & 7) + ((lane >> 4) << 3);
                int kc  = kg * 2 + ((lane >> 3) & 1);
                ldsm_x4(bx, stg + B_X + swz(row, kc));
                #pragma unroll
                for (int mt = 0; mt < 2; mt++)
                    #pragma unroll
                    for (int h = 0; h < 2; h++) {
                        float* acc = C[mt][nq * 2 + h];
                        mma16816(acc, ah[mt], &bx[h * 2]);   // Wh * X
                        mma16816(acc, al[mt], &bx[h * 2]);   // Wl * X
                    }
            }
        }
        __syncthreads();
        if (c + 3 < 18) load_chunk(c + 3);
        else            CP_COMMIT();
    }

    // ---- epilogue: BN fold -> g_f, fused 1x1 att conv -> g_att --------------
    float* s_p = (float*)smem;               // [4 warp-groups][256 px] partials
    const int wgrp = wid >> 1;               // 0,1 = branch a; 2,3 = branch b

    float scq4[2][2], sh4[2][2], wv4[2][2];
    float* frow[2][2];
    #pragma unroll
    for (int mt = 0; mt < 2; mt++)
        #pragma unroll
        for (int hr = 0; hr < 2; hr++) {
            int oc = m0 + mt * 16 + (lane >> 2) + hr * 8;
            float sc, sh;
            if (oc < 64) {
                sc = gA[oc] * rsqrtf(vA[oc] + 1e-3f);
                sh = beA[oc] - mA[oc] * sc + ba[oc] * sc;
                wv4[mt][hr] = __ldg(aw + oc);
            } else {
                int o = oc - 64;
                sc = gB[o] * rsqrtf(vB[o] + 1e-3f);
                sh = beB[o] - mB[o] * sc + bbv[o] * sc;
                wv4[mt][hr] = __ldg(bw + o);
            }
            scq4[mt][hr] = sc * (1.0f / 16.0f);
            sh4[mt][hr]  = sh;
            frow[mt][hr] = g_f + (((size_t)bb * 128 + oc) * Hc + y) * Wc;
        }

    #pragma unroll
    for (int nt = 0; nt < 16; nt++) {
        int col = n0 + nt * 8 + 2 * (lane & 3);
        float v0 = 0.f, v1 = 0.f;
        #pragma unroll
        for (int mt = 0; mt < 2; mt++)
            #pragma unroll
            for (int hr = 0; hr < 2; hr++) {
                float f0 = C[mt][nt][hr * 2 + 0] * scq4[mt][hr] + sh4[mt][hr];
                float f1 = C[mt][nt][hr * 2 + 1] * scq4[mt][hr] + sh4[mt][hr];
                *(float2*)(frow[mt][hr] + col) = make_float2(f0, f1);
                v0 += wv4[mt][hr] * f0;
                v1 += wv4[mt][hr] * f1;
            }
        // reduce across the 8 row-lanes (same lane&3)
        #pragma unroll
        for (int d = 16; d >= 4; d >>= 1) {
            v0 += __shfl_down_sync(0xffffffffu, v0, d);
            v1 += __shfl_down_sync(0xffffffffu, v1, d);
        }
        if ((lane >> 2) == 0) {
            s_p[wgrp * 256 + col]     = v0;
            s_p[wgrp * 256 + col + 1] = v1;
        }
    }
    __syncthreads();

    // finalize attention logits: +gh/gw terms +bias, BN, store
    float scA1 = __ldg(gA1) * rsqrtf(__ldg(vA1) + 1e-5f);
    float scB1 = __ldg(gB1) * rsqrtf(__ldg(vB1) + 1e-5f);
    float ghv  = axis_g(y, Hc);
    #pragma unroll
    for (int it = 0; it < 2; it++) {
        int t = tid + it * 256;
        int br = t >> 8, col = t & 255;
        float gwv = axis_g(col, Wc);
        float v = s_p[2 * br * 256 + col] + s_p[(2 * br + 1) * 256 + col];
        if (br == 0) {
            v += __ldg(aw + 64) * ghv + __ldg(aw + 65) * gwv + __ldg(abv);
            v = (v - __ldg(mA1)) * scA1 + __ldg(beA1);
        } else {
            v += __ldg(bw + 64) * ghv + __ldg(bw + 65) * gwv + __ldg(bb2);
            v = (v - __ldg(mB1)) * scB1 + __ldg(beB1);
        }
        g_att[((size_t)bb * 2 + br) * HWC + y * Wc + col] = v;
    }
}

// ============================================================================
// map_out: 3x3 conv over [att, gh, gw, pr] -> sigmoid -> scale -> out
// ============================================================================
__global__ void map_out_kernel(const float* __restrict__ wA, const float* __restrict__ wB,
                               const float* __restrict__ s1p, const float* __restrict__ s2p,
                               float* __restrict__ out, int B)
{
    int idx = blockIdx.x * blockDim.x + threadIdx.x;
    int total = B * HWC;
    if (idx >= total) return;
    int bb  = idx / HWC;
    int pix = idx - bb * HWC;
    int y = pix / Wc;
    int x = pix - y * Wc;

    float ghmin = 0.5f / (float)(Hc / 2);
    float gwmin = 0.5f / (float)(Wc / 2);
    float ghmax = axis_g(0, Hc);
    float gwmax = axis_g(0, Wc);
    float prmin = sqrtf(ghmin * ghmin + gwmin * gwmin);
    float prmax = sqrtf(ghmax * ghmax + gwmax * gwmax);
    float kk = 2.f / (prmax - prmin);
    float cc = 1.f - prmax * kk;

    float maps[2];
    #pragma unroll
    for (int br = 0; br < 2; br++) {
        const float* w = br ? wB : wA;
        const float* ab = g_att + ((size_t)bb * 2 + br) * HWC;
        float s = 0.f;
        #pragma unroll
        for (int dy = -1; dy <= 1; dy++) {
            int yy = y + dy;
            if (yy < 0 || yy >= Hc) continue;
            float ghv = axis_g(yy, Hc);
            #pragma unroll
            for (int dxx = -1; dxx <= 1; dxx++) {
                int xn = x + dxx;
                if (xn < 0 || xn >= Wc) continue;
                float av  = ab[yy * Wc + xn];
                float gwv = axis_g(xn, Wc);
                float pr  = sqrtf(ghv * ghv + gwv * gwv);
                float prn = kk * pr + cc;
                int k = (dy + 1) * 3 + (dxx + 1);
                s += __ldg(w + k)      * av
                   + __ldg(w + 9 + k)  * ghv
                   + __ldg(w + 18 + k) * gwv
                   + __ldg(w + 27 + k) * prn;
            }
        }
        float m = 1.f / (1.f + expf(-s));
        maps[br] = m * (br ? __ldg(s2p) : __ldg(s1p));
    }

    const float* f0 = g_f + (size_t)bb * 128 * HWC + pix;
    float*       o0 = out + (size_t)bb * 128 * HWC + pix;
    #pragma unroll 8
    for (int c = 0; c < 128; c++) {
        float m = (c < 64) ? maps[0] : maps[1];
        o0[(size_t)c * HWC] = f0[(size_t)c * HWC] * m;
    }
}

// ============================================================================
extern "C" void kernel_launch(void* const* d_in, const int* in_sizes, int n_in,
                              void* d_out, int out_size)
{
    const float* x        = (const float*)d_in[0];
    const float* conv_a_w = (const float*)d_in[1];
    const float* conv_a_b = (const float*)d_in[2];
    const float* conv_b_w = (const float*)d_in[3];
    const float* conv_b_b = (const float*)d_in[4];
    const float* bn_a_g   = (const float*)d_in[5];
    const float* bn_a_be  = (const float*)d_in[6];
    const float* bn_a_m   = (const float*)d_in[7];
    const float* bn_a_v   = (const float*)d_in[8];
    const float* bn_b_g   = (const float*)d_in[9];
    const float* bn_b_be  = (const float*)d_in[10];
    const float* bn_b_m   = (const float*)d_in[11];
    const float* bn_b_v   = (const float*)d_in[12];
    const float* att_a_w  = (const float*)d_in[13];
    const float* att_a_b  = (const float*)d_in[14];
    const float* att_b_w  = (const float*)d_in[15];
    const float* att_b_b  = (const float*)d_in[16];
    const float* abn_a_g  = (const float*)d_in[17];
    const float* abn_a_be = (const float*)d_in[18];
    const float* abn_a_m  = (const float*)d_in[19];
    const float* abn_a_v  = (const float*)d_in[20];
    const float* abn_b_g  = (const float*)d_in[21];
    const float* abn_b_be = (const float*)d_in[22];
    const float* abn_b_m  = (const float*)d_in[23];
    const float* abn_b_v  = (const float*)d_in[24];
    const float* attn_a_w = (const float*)d_in[25];
    const float* attn_b_w = (const float*)d_in[26];
    const float* scale1   = (const float*)d_in[27];
    const float* scale2   = (const float*)d_in[28];

    int B = in_sizes[0] / (CINc * HWC);

    cudaFuncSetAttribute(conv_mma_kernel,
                         cudaFuncAttributeMaxDynamicSharedMemorySize, SMEM_TOT);

    prep_x_kernel<<<B * 1024, 256>>>(x);
    prep_w_kernel<<<(18 * 128 * 64 + 255) / 256, 256>>>(conv_a_w, conv_b_w);

    conv_mma_kernel<<<B * 256, 256, SMEM_TOT>>>(
        conv_a_b, conv_b_b,
        bn_a_g, bn_a_be, bn_a_m, bn_a_v,
        bn_b_g, bn_b_be, bn_b_m, bn_b_v,
        att_a_w, att_a_b, att_b_w, att_b_b,
        abn_a_g, abn_a_be, abn_a_m, abn_a_v,
        abn_b_g, abn_b_be, abn_b_m, abn_b_v);

    int total = B * HWC;
    int nb = (total + 255) / 256;
    map_out_kernel<<<nb, 256>>>(attn_a_w, attn_b_w, scale1, scale2,
                                (float*)d_out, B);
}

// round 7
// speedup vs baseline: 5.2158x; 1.0515x over previous
#include <cuda_runtime.h>
#include <cuda_fp16.h>
#include <math.h>
#include <stdint.h>

#define Hc  256
#define Wc  256
#define CINc 128
#define HWC (Hc * Wc)

// ---------------- scratch (static device globals; no runtime allocation) ----
__device__ __align__(256) __half g_fh[(size_t)4 * 128 * HWC];  // post-BN features NCHW fp16
__device__ float g_att[(size_t)4 * 2 * HWC];                   // attention logits
__device__ float g_map[(size_t)4 * 2 * HWC];                   // sigmoid maps * scale
__device__ __align__(256) __half g_xh[(size_t)4 * HWC * 128];  // x fp16, NHWC
__device__ __align__(256) __half g_whi[18 * 128 * 64];         // (W*16) hi [chunk][oc][k]
__device__ __align__(256) __half g_wlo[18 * 128 * 64];         // (W*16) lo

// ---------------- helpers ----------------------------------------------------
__device__ __forceinline__ uint32_t smem_u32(const void* p) {
    uint32_t a;
    asm("{ .reg .u64 t; cvta.to.shared.u64 t, %1; cvt.u32.u64 %0, t; }" : "=r"(a) : "l"(p));
    return a;
}
__device__ __forceinline__ void cp16(uint32_t dst, const void* src, uint32_t sz) {
    asm volatile("cp.async.cg.shared.global [%0], [%1], 16, %2;"
                 :: "r"(dst), "l"(src), "r"(sz));
}
#define CP_COMMIT() asm volatile("cp.async.commit_group;" ::: "memory")
#define CP_WAIT2()  asm volatile("cp.async.wait_group 2;" ::: "memory")

__device__ __forceinline__ void ldsm_x4(uint32_t* r, uint32_t a) {
    asm volatile("ldmatrix.sync.aligned.m8n8.x4.shared.b16 {%0,%1,%2,%3}, [%4];"
                 : "=r"(r[0]), "=r"(r[1]), "=r"(r[2]), "=r"(r[3]) : "r"(a));
}
__device__ __forceinline__ void mma16816(float* d, const uint32_t* a, const uint32_t* b) {
    asm volatile("mma.sync.aligned.m16n8k16.row.col.f32.f16.f16.f32 "
                 "{%0,%1,%2,%3},{%4,%5,%6,%7},{%8,%9},{%0,%1,%2,%3};"
                 : "+f"(d[0]), "+f"(d[1]), "+f"(d[2]), "+f"(d[3])
                 : "r"(a[0]), "r"(a[1]), "r"(a[2]), "r"(a[3]), "r"(b[0]), "r"(b[1]));
}

// position helper (matches reference)
__device__ __forceinline__ float axis_g(int i, int n) {
    float off = ((n & 1) == 0) ? 0.5f : 0.0f;
    return fabsf((float)i - (float)(n / 2) + off) / (float)(n / 2);
}

// ============================================================================
// prep_x: NCHW fp32 -> NHWC fp16 (smem transpose, coalesced both sides)
// ============================================================================
__global__ __launch_bounds__(256)
void prep_x_kernel(const float* __restrict__ x)
{
    __shared__ __half s_h[64 * 136];
    int blk = blockIdx.x;
    int bb  = blk >> 10;
    int px0 = (blk & 1023) * 64;
    int tid = threadIdx.x;
    int p = tid & 63, cq = tid >> 6;

    const float* xb = x + (size_t)bb * CINc * HWC;
    for (int c0 = 0; c0 < CINc; c0 += 4) {
        int c = c0 + cq;
        s_h[p * 136 + c] = __float2half(xb[(size_t)c * HWC + px0 + p]);
    }
    __syncthreads();
    for (int i = tid; i < 64 * 16; i += 256) {
        int p2 = i >> 4, j = i & 15;
        uint4 v = *(const uint4*)&s_h[p2 * 136 + j * 8];
        size_t e = ((size_t)bb * HWC + px0 + p2) * 128 + j * 8;
        *(uint4*)(g_xh + e) = v;
    }
}

// ============================================================================
// prep_w: fp32 weights *16 -> fp16 hi/lo, [chunk18][128oc][64k]
// ============================================================================
__global__ void prep_w_kernel(const float* __restrict__ wa, const float* __restrict__ wb)
{
    int idx = blockIdx.x * 256 + threadIdx.x;
    if (idx >= 18 * 128 * 64) return;
    int k  = idx & 63;
    int oc = (idx >> 6) & 127;
    int c  = idx >> 13;
    int t  = c >> 1, hf = c & 1;
    int cin = hf * 64 + k;
    float w = (oc < 64) ? wa[((size_t)oc * CINc + cin) * 9 + t]
                        : wb[((size_t)(oc - 64) * CINc + cin) * 9 + t];
    w *= 16.0f;                              // keep W-lo normal in fp16
    __half h = __float2half(w);
    __half l = __float2half(w - __half2float(h));
    g_whi[idx] = h;
    g_wlo[idx] = l;
}

// ============================================================================
// conv_mma: implicit GEMM via mma.sync fp16 (2-term W hi/lo split, fp32 accum)
//   CTA: 128 oc x 256 px (one full output row); 16 warps, warp tile 32x64
//   K: 18 chunks of 64 (tap x cin-half); cp.async 3-stage pipeline
//   Epilogue: BN fold -> g_fh (fp16), PLUS fused 1x1 attention conv -> g_att
// ============================================================================
#define A_HI 0
#define A_LO 16384
#define B_X  32768
#define STAGE 65536
#define SMEM_TOT (3 * STAGE)

// swizzled 16B offset inside a [row][64k] fp16 tile (row stride 128B)
__device__ __forceinline__ uint32_t swz(int row, int j16) {
    return (uint32_t)(row * 128 + ((j16 ^ (row & 7)) << 4));
}

__global__ __launch_bounds__(512, 1)
void conv_mma_kernel(const float* __restrict__ ba,  const float* __restrict__ bbv,
                     const float* __restrict__ gA,  const float* __restrict__ beA,
                     const float* __restrict__ mA,  const float* __restrict__ vA,
                     const float* __restrict__ gB,  const float* __restrict__ beB,
                     const float* __restrict__ mB,  const float* __restrict__ vB,
                     const float* __restrict__ aw,  const float* __restrict__ abv,
                     const float* __restrict__ bw,  const float* __restrict__ bb2,
                     const float* __restrict__ gA1, const float* __restrict__ beA1,
                     const float* __restrict__ mA1, const float* __restrict__ vA1,
                     const float* __restrict__ gB1, const float* __restrict__ beB1,
                     const float* __restrict__ mB1, const float* __restrict__ vB1)
{
    extern __shared__ char smem[];
    const uint32_t sb = smem_u32(smem);
    const int tid  = threadIdx.x;
    const int wid  = tid >> 5, lane = tid & 31;
    const int bb   = blockIdx.x >> 8;
    const int y    = blockIdx.x & 255;
    const int m0   = (wid >> 2) * 32;         // warp oc base (4 m-groups)
    const int n0   = (wid & 3) * 64;          // warp px base (4 n-groups)

    float C[2][8][4];
    #pragma unroll
    for (int mt = 0; mt < 2; mt++)
        #pragma unroll
        for (int nt = 0; nt < 8; nt++)
            #pragma unroll
            for (int q = 0; q < 4; q++) C[mt][nt][q] = 0.f;

    // ---- chunk loader: cp.async into stage, one commit ----
    auto load_chunk = [&](int c) {
        uint32_t stg = sb + (uint32_t)(c % 3) * STAGE;
        int t  = c >> 1, hf = c & 1;
        int yy = y + t / 3 - 1;
        int dx = t % 3 - 1;
        bool vy = (yy >= 0) && (yy < Hc);
        size_t arow = (size_t)c * 8192;                       // A chunk base (elems)
        size_t brow = ((size_t)(bb * Hc + yy) * Wc) * 128;    // B row base (elems)
        #pragma unroll
        for (int i = 0; i < 2; i++) {                         // A hi+lo: 128 rows
            int idx = tid + i * 512;
            int row = idx >> 3, j = idx & 7;
            cp16(stg + A_HI + swz(row, j), g_whi + arow + idx * 8, 16);
            cp16(stg + A_LO + swz(row, j), g_wlo + arow + idx * 8, 16);
        }
        #pragma unroll
        for (int i = 0; i < 4; i++) {                         // B: 256 px rows
            int idx = tid + i * 512;
            int row = idx >> 3, j = idx & 7;
            int xx = row + dx;
            bool ok = vy && (xx >= 0) && (xx < Wc);
            size_t e = ok ? (brow + (size_t)xx * 128 + hf * 64 + j * 8) : 0;
            cp16(stg + B_X + swz(row, j), g_xh + e, ok ? 16u : 0u);
        }
        CP_COMMIT();
    };

    // prologue: prefetch chunks 0..2
    load_chunk(0);
    load_chunk(1);
    load_chunk(2);

    for (int c = 0; c < 18; c++) {
        CP_WAIT2();
        __syncthreads();
        const uint32_t stg = sb + (uint32_t)(c % 3) * STAGE;

        #pragma unroll
        for (int kg = 0; kg < 4; kg++) {
            uint32_t ah[2][4], al[2][4];
            #pragma unroll
            for (int mt = 0; mt < 2; mt++) {
                int row = m0 + mt * 16 + (lane & 15);
                int kc  = kg * 2 + (lane >> 4);
                uint32_t off = swz(row, kc);
                ldsm_x4(ah[mt], stg + A_HI + off);
                ldsm_x4(al[mt], stg + A_LO + off);
            }
            #pragma unroll
            for (int nq = 0; nq < 4; nq++) {
                uint32_t bx[4];
                int row = n0 + nq * 16 + (lane & 7) + ((lane >> 4) << 3);
                int kc  = kg * 2 + ((lane >> 3) & 1);
                ldsm_x4(bx, stg + B_X + swz(row, kc));
                #pragma unroll
                for (int mt = 0; mt < 2; mt++)
                    #pragma unroll
                    for (int h = 0; h < 2; h++) {
                        float* acc = C[mt][nq * 2 + h];
                        mma16816(acc, ah[mt], &bx[h * 2]);   // Wh * X
                        mma16816(acc, al[mt], &bx[h * 2]);   // Wl * X
                    }
            }
        }
        __syncthreads();
        if (c + 3 < 18) load_chunk(c + 3);
        else            CP_COMMIT();
    }

    // ---- epilogue: BN fold -> g_fh (fp16), fused 1x1 att conv -> g_att ------
    float* s_p = (float*)smem;               // [4 m-groups][256 px] partials
    const int mg = wid >> 2;                 // m-group: 0,1 = branch a; 2,3 = b

    float scq4[2][2], sh4[2][2], wv4[2][2];
    __half* frow[2][2];
    #pragma unroll
    for (int mt = 0; mt < 2; mt++)
        #pragma unroll
        for (int hr = 0; hr < 2; hr++) {
            int oc = m0 + mt * 16 + (lane >> 2) + hr * 8;
            float sc, sh;
            if (oc < 64) {
                sc = gA[oc] * rsqrtf(vA[oc] + 1e-3f);
                sh = beA[oc] - mA[oc] * sc + ba[oc] * sc;
                wv4[mt][hr] = __ldg(aw + oc);
            } else {
                int o = oc - 64;
                sc = gB[o] * rsqrtf(vB[o] + 1e-3f);
                sh = beB[o] - mB[o] * sc + bbv[o] * sc;
                wv4[mt][hr] = __ldg(bw + o);
            }
            scq4[mt][hr] = sc * (1.0f / 16.0f);
            sh4[mt][hr]  = sh;
            frow[mt][hr] = g_fh + (((size_t)bb * 128 + oc) * Hc + y) * Wc;
        }

    #pragma unroll
    for (int nt = 0; nt < 8; nt++) {
        int col = n0 + nt * 8 + 2 * (lane & 3);
        float v0 = 0.f, v1 = 0.f;
        #pragma unroll
        for (int mt = 0; mt < 2; mt++)
            #pragma unroll
            for (int hr = 0; hr < 2; hr++) {
                float f0 = C[mt][nt][hr * 2 + 0] * scq4[mt][hr] + sh4[mt][hr];
                float f1 = C[mt][nt][hr * 2 + 1] * scq4[mt][hr] + sh4[mt][hr];
                *(__half2*)(frow[mt][hr] + col) = __floats2half2_rn(f0, f1);
                v0 += wv4[mt][hr] * f0;
                v1 += wv4[mt][hr] * f1;
            }
        // reduce across the 8 row-lanes (same lane&3)
        #pragma unroll
        for (int d = 16; d >= 4; d >>= 1) {
            v0 += __shfl_down_sync(0xffffffffu, v0, d);
            v1 += __shfl_down_sync(0xffffffffu, v1, d);
        }
        if ((lane >> 2) == 0) {
            s_p[mg * 256 + col]     = v0;
            s_p[mg * 256 + col + 1] = v1;
        }
    }
    __syncthreads();

    // finalize attention logits: +gh/gw terms +bias, BN, store (512 thr = 2x256)
    {
        int br = tid >> 8, col = tid & 255;
        float scA1 = __ldg(gA1) * rsqrtf(__ldg(vA1) + 1e-5f);
        float scB1 = __ldg(gB1) * rsqrtf(__ldg(vB1) + 1e-5f);
        float ghv  = axis_g(y, Hc);
        float gwv  = axis_g(col, Wc);
        float v = s_p[2 * br * 256 + col] + s_p[(2 * br + 1) * 256 + col];
        if (br == 0) {
            v += __ldg(aw + 64) * ghv + __ldg(aw + 65) * gwv + __ldg(abv);
            v = (v - __ldg(mA1)) * scA1 + __ldg(beA1);
        } else {
            v += __ldg(bw + 64) * ghv + __ldg(bw + 65) * gwv + __ldg(bb2);
            v = (v - __ldg(mB1)) * scB1 + __ldg(beB1);
        }
        g_att[((size_t)bb * 2 + br) * HWC + y * Wc + col] = v;
    }
}

// ============================================================================
// map_kernel: 3x3 conv over [att, gh, gw, pr] -> sigmoid * scale -> g_map
// ============================================================================
__global__ void map_kernel(const float* __restrict__ wA, const float* __restrict__ wB,
                           const float* __restrict__ s1p, const float* __restrict__ s2p,
                           int B)
{
    int idx = blockIdx.x * blockDim.x + threadIdx.x;
    int total = B * HWC;
    if (idx >= total) return;
    int bb  = idx / HWC;
    int pix = idx - bb * HWC;
    int y = pix / Wc;
    int x = pix - y * Wc;

    float ghmin = 0.5f / (float)(Hc / 2);
    float gwmin = 0.5f / (float)(Wc / 2);
    float ghmax = axis_g(0, Hc);
    float gwmax = axis_g(0, Wc);
    float prmin = sqrtf(ghmin * ghmin + gwmin * gwmin);
    float prmax = sqrtf(ghmax * ghmax + gwmax * gwmax);
    float kk = 2.f / (prmax - prmin);
    float cc = 1.f - prmax * kk;

    #pragma unroll
    for (int br = 0; br < 2; br++) {
        const float* w = br ? wB : wA;
        const float* ab = g_att + ((size_t)bb * 2 + br) * HWC;
        float s = 0.f;
        #pragma unroll
        for (int dy = -1; dy <= 1; dy++) {
            int yy = y + dy;
            if (yy < 0 || yy >= Hc) continue;
            float ghv = axis_g(yy, Hc);
            #pragma unroll
            for (int dxx = -1; dxx <= 1; dxx++) {
                int xn = x + dxx;
                if (xn < 0 || xn >= Wc) continue;
                float av  = ab[yy * Wc + xn];
                float gwv = axis_g(xn, Wc);
                float pr  = sqrtf(ghv * ghv + gwv * gwv);
                float prn = kk * pr + cc;
                int k = (dy + 1) * 3 + (dxx + 1);
                s += __ldg(w + k)      * av
                   + __ldg(w + 9 + k)  * ghv
                   + __ldg(w + 18 + k) * gwv
                   + __ldg(w + 27 + k) * prn;
            }
        }
        float m = 1.f / (1.f + expf(-s));
        g_map[((size_t)bb * 2 + br) * HWC + pix] =
            m * (br ? __ldg(s2p) : __ldg(s1p));
    }
}

// ============================================================================
// scale_kernel: out[c][p] = fp16(f)[c][p] * map[br][p]   (4 px / thread)
// ============================================================================
__global__ __launch_bounds__(256)
void scale_kernel(float* __restrict__ out, int B)
{
    int idx = blockIdx.x * blockDim.x + threadIdx.x;
    int total = B * (HWC / 4);
    if (idx >= total) return;
    int bb = idx / (HWC / 4);
    int p4 = (idx - bb * (HWC / 4)) * 4;

    float4 ma = *(const float4*)(g_map + ((size_t)bb * 2 + 0) * HWC + p4);
    float4 mb = *(const float4*)(g_map + ((size_t)bb * 2 + 1) * HWC + p4);

    const __half* f0 = g_fh + (size_t)bb * 128 * HWC + p4;
    float*        o0 = out  + (size_t)bb * 128 * HWC + p4;
    #pragma unroll 8
    for (int c = 0; c < 128; c++) {
        float4 m = (c < 64) ? ma : mb;
        uint2 v = *(const uint2*)(f0 + (size_t)c * HWC);
        __half2 h01 = *(__half2*)&v.x;
        __half2 h23 = *(__half2*)&v.y;
        float4 r;
        r.x = __low2float(h01)  * m.x;
        r.y = __high2float(h01) * m.y;
        r.z = __low2float(h23)  * m.z;
        r.w = __high2float(h23) * m.w;
        *(float4*)(o0 + (size_t)c * HWC) = r;
    }
}

// ============================================================================
extern "C" void kernel_launch(void* const* d_in, const int* in_sizes, int n_in,
                              void* d_out, int out_size)
{
    const float* x        = (const float*)d_in[0];
    const float* conv_a_w = (const float*)d_in[1];
    const float* conv_a_b = (const float*)d_in[2];
    const float* conv_b_w = (const float*)d_in[3];
    const float* conv_b_b = (const float*)d_in[4];
    const float* bn_a_g   = (const float*)d_in[5];
    const float* bn_a_be  = (const float*)d_in[6];
    const float* bn_a_m   = (const float*)d_in[7];
    const float* bn_a_v   = (const float*)d_in[8];
    const float* bn_b_g   = (const float*)d_in[9];
    const float* bn_b_be  = (const float*)d_in[10];
    const float* bn_b_m   = (const float*)d_in[11];
    const float* bn_b_v   = (const float*)d_in[12];
    const float* att_a_w  = (const float*)d_in[13];
    const float* att_a_b  = (const float*)d_in[14];
    const float* att_b_w  = (const float*)d_in[15];
    const float* att_b_b  = (const float*)d_in[16];
    const float* abn_a_g  = (const float*)d_in[17];
    const float* abn_a_be = (const float*)d_in[18];
    const float* abn_a_m  = (const float*)d_in[19];
    const float* abn_a_v  = (const float*)d_in[20];
    const float* abn_b_g  = (const float*)d_in[21];
    const float* abn_b_be = (const float*)d_in[22];
    const float* abn_b_m  = (const float*)d_in[23];
    const float* abn_b_v  = (const float*)d_in[24];
    const float* attn_a_w = (const float*)d_in[25];
    const float* attn_b_w = (const float*)d_in[26];
    const float* scale1   = (const float*)d_in[27];
    const float* scale2   = (const float*)d_in[28];

    int B = in_sizes[0] / (CINc * HWC);

    cudaFuncSetAttribute(conv_mma_kernel,
                         cudaFuncAttributeMaxDynamicSharedMemorySize, SMEM_TOT);

    prep_x_kernel<<<B * 1024, 256>>>(x);
    prep_w_kernel<<<(18 * 128 * 64 + 255) / 256, 256>>>(conv_a_w, conv_b_w);

    conv_mma_kernel<<<B * 256, 512, SMEM_TOT>>>(
        conv_a_b, conv_b_b,
        bn_a_g, bn_a_be, bn_a_m, bn_a_v,
        bn_b_g, bn_b_be, bn_b_m, bn_b_v,
        att_a_w, att_a_b, att_b_w, att_b_b,
        abn_a_g, abn_a_be, abn_a_m, abn_a_v,
        abn_b_g, abn_b_be, abn_b_m, abn_b_v);

    int total = B * HWC;
    int nb = (total + 255) / 256;
    map_kernel<<<nb, 256>>>(attn_a_w, attn_b_w, scale1, scale2, B);

    int nb4 = (B * (HWC / 4) + 255) / 256;
    scale_kernel<<<nb4, 256>>>((float*)d_out, B);
}

// round 8
// speedup vs baseline: 7.2181x; 1.3839x over previous
#include <cuda_runtime.h>
#include <cuda_fp16.h>
#include <math.h>
#include <stdint.h>

#define Hc  256
#define Wc  256
#define CINc 128
#define HWC (Hc * Wc)

// ---------------- scratch (static device globals; no runtime allocation) ----
__device__ __align__(256) __half g_fh[(size_t)4 * 128 * HWC];  // post-BN features NCHW fp16
__device__ float g_att[(size_t)4 * 2 * HWC];                   // attention logits
__device__ float g_map[(size_t)4 * 2 * HWC];                   // sigmoid maps * scale
__device__ __align__(256) __half g_xh[(size_t)4 * HWC * 128];  // x fp16, NHWC
__device__ __align__(256) __half g_wh[18 * 128 * 64];          // W fp16 [chunk][oc][k]

// ---------------- helpers ----------------------------------------------------
__device__ __forceinline__ uint32_t smem_u32(const void* p) {
    uint32_t a;
    asm("{ .reg .u64 t; cvta.to.shared.u64 t, %1; cvt.u32.u64 %0, t; }" : "=r"(a) : "l"(p));
    return a;
}
__device__ __forceinline__ void cp16(uint32_t dst, const void* src, uint32_t sz) {
    asm volatile("cp.async.cg.shared.global [%0], [%1], 16, %2;"
                 :: "r"(dst), "l"(src), "r"(sz));
}
#define CP_COMMIT() asm volatile("cp.async.commit_group;" ::: "memory")
#define CP_WAIT2()  asm volatile("cp.async.wait_group 2;" ::: "memory")

__device__ __forceinline__ void ldsm_x4(uint32_t* r, uint32_t a) {
    asm volatile("ldmatrix.sync.aligned.m8n8.x4.shared.b16 {%0,%1,%2,%3}, [%4];"
                 : "=r"(r[0]), "=r"(r[1]), "=r"(r[2]), "=r"(r[3]) : "r"(a));
}
__device__ __forceinline__ void mma16816(float* d, const uint32_t* a, const uint32_t* b) {
    asm volatile("mma.sync.aligned.m16n8k16.row.col.f32.f16.f16.f32 "
                 "{%0,%1,%2,%3},{%4,%5,%6,%7},{%8,%9},{%0,%1,%2,%3};"
                 : "+f"(d[0]), "+f"(d[1]), "+f"(d[2]), "+f"(d[3])
                 : "r"(a[0]), "r"(a[1]), "r"(a[2]), "r"(a[3]), "r"(b[0]), "r"(b[1]));
}

// position helper (matches reference)
__device__ __forceinline__ float axis_g(int i, int n) {
    float off = ((n & 1) == 0) ? 0.5f : 0.0f;
    return fabsf((float)i - (float)(n / 2) + off) / (float)(n / 2);
}

// ============================================================================
// prep_x: NCHW fp32 -> NHWC fp16 (smem transpose, coalesced both sides)
// ============================================================================
__global__ __launch_bounds__(256)
void prep_x_kernel(const float* __restrict__ x)
{
    __shared__ __half s_h[64 * 136];
    int blk = blockIdx.x;
    int bb  = blk >> 10;
    int px0 = (blk & 1023) * 64;
    int tid = threadIdx.x;
    int p = tid & 63, cq = tid >> 6;

    const float* xb = x + (size_t)bb * CINc * HWC;
    for (int c0 = 0; c0 < CINc; c0 += 4) {
        int c = c0 + cq;
        s_h[p * 136 + c] = __float2half(xb[(size_t)c * HWC + px0 + p]);
    }
    __syncthreads();
    for (int i = tid; i < 64 * 16; i += 256) {
        int p2 = i >> 4, j = i & 15;
        uint4 v = *(const uint4*)&s_h[p2 * 136 + j * 8];
        size_t e = ((size_t)bb * HWC + px0 + p2) * 128 + j * 8;
        *(uint4*)(g_xh + e) = v;
    }
}

// ============================================================================
// prep_w: fp32 weights -> fp16, [chunk18][128oc][64k]
// ============================================================================
__global__ void prep_w_kernel(const float* __restrict__ wa, const float* __restrict__ wb)
{
    int idx = blockIdx.x * 256 + threadIdx.x;
    if (idx >= 18 * 128 * 64) return;
    int k  = idx & 63;
    int oc = (idx >> 6) & 127;
    int c  = idx >> 13;
    int t  = c >> 1, hf = c & 1;
    int cin = hf * 64 + k;
    float w = (oc < 64) ? wa[((size_t)oc * CINc + cin) * 9 + t]
                        : wb[((size_t)(oc - 64) * CINc + cin) * 9 + t];
    g_wh[idx] = __float2half(w);
}

// ============================================================================
// conv_mma: implicit GEMM via mma.sync fp16 (single term, fp32 accum)
//   CTA: 128 oc x 256 px (one full output row); 16 warps, warp tile 32x64
//   K: 18 chunks of 64 (tap x cin-half); cp.async 3-stage pipeline
//   Epilogue: BN fold -> g_fh (fp16), PLUS fused 1x1 attention conv -> g_att
// ============================================================================
#define A_W  0
#define B_X  16384
#define STAGE 49152
#define SMEM_TOT (3 * STAGE)

// swizzled 16B offset inside a [row][64k] fp16 tile (row stride 128B)
__device__ __forceinline__ uint32_t swz(int row, int j16) {
    return (uint32_t)(row * 128 + ((j16 ^ (row & 7)) << 4));
}

__global__ __launch_bounds__(512, 1)
void conv_mma_kernel(const float* __restrict__ ba,  const float* __restrict__ bbv,
                     const float* __restrict__ gA,  const float* __restrict__ beA,
                     const float* __restrict__ mA,  const float* __restrict__ vA,
                     const float* __restrict__ gB,  const float* __restrict__ beB,
                     const float* __restrict__ mB,  const float* __restrict__ vB,
                     const float* __restrict__ aw,  const float* __restrict__ abv,
                     const float* __restrict__ bw,  const float* __restrict__ bb2,
                     const float* __restrict__ gA1, const float* __restrict__ beA1,
                     const float* __restrict__ mA1, const float* __restrict__ vA1,
                     const float* __restrict__ gB1, const float* __restrict__ beB1,
                     const float* __restrict__ mB1, const float* __restrict__ vB1)
{
    extern __shared__ char smem[];
    const uint32_t sb = smem_u32(smem);
    const int tid  = threadIdx.x;
    const int wid  = tid >> 5, lane = tid & 31;
    const int bb   = blockIdx.x >> 8;
    const int y    = blockIdx.x & 255;
    const int m0   = (wid >> 2) * 32;         // warp oc base (4 m-groups)
    const int n0   = (wid & 3) * 64;          // warp px base (4 n-groups)

    float C[2][8][4];
    #pragma unroll
    for (int mt = 0; mt < 2; mt++)
        #pragma unroll
        for (int nt = 0; nt < 8; nt++)
            #pragma unroll
            for (int q = 0; q < 4; q++) C[mt][nt][q] = 0.f;

    // ---- chunk loader: cp.async into stage, one commit ----
    auto load_chunk = [&](int c) {
        uint32_t stg = sb + (uint32_t)(c % 3) * STAGE;
        int t  = c >> 1, hf = c & 1;
        int yy = y + t / 3 - 1;
        int dx = t % 3 - 1;
        bool vy = (yy >= 0) && (yy < Hc);
        size_t arow = (size_t)c * 8192;                       // A chunk base (elems)
        size_t brow = ((size_t)(bb * Hc + yy) * Wc) * 128;    // B row base (elems)
        #pragma unroll
        for (int i = 0; i < 2; i++) {                         // A: 128 oc rows
            int idx = tid + i * 512;
            int row = idx >> 3, j = idx & 7;
            cp16(stg + A_W + swz(row, j), g_wh + arow + idx * 8, 16);
        }
        #pragma unroll
        for (int i = 0; i < 4; i++) {                         // B: 256 px rows
            int idx = tid + i * 512;
            int row = idx >> 3, j = idx & 7;
            int xx = row + dx;
            bool ok = vy && (xx >= 0) && (xx < Wc);
            size_t e = ok ? (brow + (size_t)xx * 128 + hf * 64 + j * 8) : 0;
            cp16(stg + B_X + swz(row, j), g_xh + e, ok ? 16u : 0u);
        }
        CP_COMMIT();
    };

    // prologue: prefetch chunks 0..2
    load_chunk(0);
    load_chunk(1);
    load_chunk(2);

    for (int c = 0; c < 18; c++) {
        CP_WAIT2();
        __syncthreads();
        const uint32_t stg = sb + (uint32_t)(c % 3) * STAGE;

        #pragma unroll
        for (int kg = 0; kg < 4; kg++) {
            uint32_t ah[2][4];
            #pragma unroll
            for (int mt = 0; mt < 2; mt++) {
                int row = m0 + mt * 16 + (lane & 15);
                int kc  = kg * 2 + (lane >> 4);
                ldsm_x4(ah[mt], stg + A_W + swz(row, kc));
            }
            #pragma unroll
            for (int nq = 0; nq < 4; nq++) {
                uint32_t bx[4];
                int row = n0 + nq * 16 + (lane & 7) + ((lane >> 4) << 3);
                int kc  = kg * 2 + ((lane >> 3) & 1);
                ldsm_x4(bx, stg + B_X + swz(row, kc));
                #pragma unroll
                for (int mt = 0; mt < 2; mt++)
                    #pragma unroll
                    for (int h = 0; h < 2; h++)
                        mma16816(C[mt][nq * 2 + h], ah[mt], &bx[h * 2]);
            }
        }
        __syncthreads();
        if (c + 3 < 18) load_chunk(c + 3);
        else            CP_COMMIT();
    }

    // ---- epilogue: BN fold -> g_fh (fp16), fused 1x1 att conv -> g_att ------
    float* s_p = (float*)smem;               // [4 m-groups][256 px] partials
    const int mg = wid >> 2;                 // m-group: 0,1 = branch a; 2,3 = b

    float scq4[2][2], sh4[2][2], wv4[2][2];
    __half* frow[2][2];
    #pragma unroll
    for (int mt = 0; mt < 2; mt++)
        #pragma unroll
        for (int hr = 0; hr < 2; hr++) {
            int oc = m0 + mt * 16 + (lane >> 2) + hr * 8;
            float sc, sh;
            if (oc < 64) {
                sc = gA[oc] * rsqrtf(vA[oc] + 1e-3f);
                sh = beA[oc] - mA[oc] * sc + ba[oc] * sc;
                wv4[mt][hr] = __ldg(aw + oc);
            } else {
                int o = oc - 64;
                sc = gB[o] * rsqrtf(vB[o] + 1e-3f);
                sh = beB[o] - mB[o] * sc + bbv[o] * sc;
                wv4[mt][hr] = __ldg(bw + o);
            }
            scq4[mt][hr] = sc;
            sh4[mt][hr]  = sh;
            frow[mt][hr] = g_fh + (((size_t)bb * 128 + oc) * Hc + y) * Wc;
        }

    #pragma unroll
    for (int nt = 0; nt < 8; nt++) {
        int col = n0 + nt * 8 + 2 * (lane & 3);
        float v0 = 0.f, v1 = 0.f;
        #pragma unroll
        for (int mt = 0; mt < 2; mt++)
            #pragma unroll
            for (int hr = 0; hr < 2; hr++) {
                float f0 = C[mt][nt][hr * 2 + 0] * scq4[mt][hr] + sh4[mt][hr];
                float f1 = C[mt][nt][hr * 2 + 1] * scq4[mt][hr] + sh4[mt][hr];
                *(__half2*)(frow[mt][hr] + col) = __floats2half2_rn(f0, f1);
                v0 += wv4[mt][hr] * f0;
                v1 += wv4[mt][hr] * f1;
            }
        // reduce across the 8 row-lanes (same lane&3)
        #pragma unroll
        for (int d = 16; d >= 4; d >>= 1) {
            v0 += __shfl_down_sync(0xffffffffu, v0, d);
            v1 += __shfl_down_sync(0xffffffffu, v1, d);
        }
        if ((lane >> 2) == 0) {
            s_p[mg * 256 + col]     = v0;
            s_p[mg * 256 + col + 1] = v1;
        }
    }
    __syncthreads();

    // finalize attention logits: +gh/gw terms +bias, BN, store (512 thr = 2x256)
    {
        int br = tid >> 8, col = tid & 255;
        float scA1 = __ldg(gA1) * rsqrtf(__ldg(vA1) + 1e-5f);
        float scB1 = __ldg(gB1) * rsqrtf(__ldg(vB1) + 1e-5f);
        float ghv  = axis_g(y, Hc);
        float gwv  = axis_g(col, Wc);
        float v = s_p[2 * br * 256 + col] + s_p[(2 * br + 1) * 256 + col];
        if (br == 0) {
            v += __ldg(aw + 64) * ghv + __ldg(aw + 65) * gwv + __ldg(abv);
            v = (v - __ldg(mA1)) * scA1 + __ldg(beA1);
        } else {
            v += __ldg(bw + 64) * ghv + __ldg(bw + 65) * gwv + __ldg(bb2);
            v = (v - __ldg(mB1)) * scB1 + __ldg(beB1);
        }
        g_att[((size_t)bb * 2 + br) * HWC + y * Wc + col] = v;
    }
}

// ============================================================================
// map_kernel: 3x3 conv over [att, gh, gw, pr] -> sigmoid * scale -> g_map
// ============================================================================
__global__ void map_kernel(const float* __restrict__ wA, const float* __restrict__ wB,
                           const float* __restrict__ s1p, const float* __restrict__ s2p,
                           int B)
{
    int idx = blockIdx.x * blockDim.x + threadIdx.x;
    int total = B * HWC;
    if (idx >= total) return;
    int bb  = idx / HWC;
    int pix = idx - bb * HWC;
    int y = pix / Wc;
    int x = pix - y * Wc;

    float ghmin = 0.5f / (float)(Hc / 2);
    float gwmin = 0.5f / (float)(Wc / 2);
    float ghmax = axis_g(0, Hc);
    float gwmax = axis_g(0, Wc);
    float prmin = sqrtf(ghmin * ghmin + gwmin * gwmin);
    float prmax = sqrtf(ghmax * ghmax + gwmax * gwmax);
    float kk = 2.f / (prmax - prmin);
    float cc = 1.f - prmax * kk;

    #pragma unroll
    for (int br = 0; br < 2; br++) {
        const float* w = br ? wB : wA;
        const float* ab = g_att + ((size_t)bb * 2 + br) * HWC;
        float s = 0.f;
        #pragma unroll
        for (int dy = -1; dy <= 1; dy++) {
            int yy = y + dy;
            if (yy < 0 || yy >= Hc) continue;
            float ghv = axis_g(yy, Hc);
            #pragma unroll
            for (int dxx = -1; dxx <= 1; dxx++) {
                int xn = x + dxx;
                if (xn < 0 || xn >= Wc) continue;
                float av  = ab[yy * Wc + xn];
                float gwv = axis_g(xn, Wc);
                float pr  = sqrtf(ghv * ghv + gwv * gwv);
                float prn = kk * pr + cc;
                int k = (dy + 1) * 3 + (dxx + 1);
                s += __ldg(w + k)      * av
                   + __ldg(w + 9 + k)  * ghv
                   + __ldg(w + 18 + k) * gwv
                   + __ldg(w + 27 + k) * prn;
            }
        }
        float m = 1.f / (1.f + expf(-s));
        g_map[((size_t)bb * 2 + br) * HWC + pix] =
            m * (br ? __ldg(s2p) : __ldg(s1p));
    }
}

// ============================================================================
// scale_kernel: out[c][p] = fp16(f)[c][p] * map[br][p]   (4 px / thread)
// ============================================================================
__global__ __launch_bounds__(256)
void scale_kernel(float* __restrict__ out, int B)
{
    int idx = blockIdx.x * blockDim.x + threadIdx.x;
    int total = B * (HWC / 4);
    if (idx >= total) return;
    int bb = idx / (HWC / 4);
    int p4 = (idx - bb * (HWC / 4)) * 4;

    float4 ma = *(const float4*)(g_map + ((size_t)bb * 2 + 0) * HWC + p4);
    float4 mb = *(const float4*)(g_map + ((size_t)bb * 2 + 1) * HWC + p4);

    const __half* f0 = g_fh + (size_t)bb * 128 * HWC + p4;
    float*        o0 = out  + (size_t)bb * 128 * HWC + p4;
    #pragma unroll 8
    for (int c = 0; c < 128; c++) {
        float4 m = (c < 64) ? ma : mb;
        uint2 v = *(const uint2*)(f0 + (size_t)c * HWC);
        __half2 h01 = *(__half2*)&v.x;
        __half2 h23 = *(__half2*)&v.y;
        float4 r;
        r.x = __low2float(h01)  * m.x;
        r.y = __high2float(h01) * m.y;
        r.z = __low2float(h23)  * m.z;
        r.w = __high2float(h23) * m.w;
        *(float4*)(o0 + (size_t)c * HWC) = r;
    }
}

// ============================================================================
extern "C" void kernel_launch(void* const* d_in, const int* in_sizes, int n_in,
                              void* d_out, int out_size)
{
    const float* x        = (const float*)d_in[0];
    const float* conv_a_w = (const float*)d_in[1];
    const float* conv_a_b = (const float*)d_in[2];
    const float* conv_b_w = (const float*)d_in[3];
    const float* conv_b_b = (const float*)d_in[4];
    const float* bn_a_g   = (const float*)d_in[5];
    const float* bn_a_be  = (const float*)d_in[6];
    const float* bn_a_m   = (const float*)d_in[7];
    const float* bn_a_v   = (const float*)d_in[8];
    const float* bn_b_g   = (const float*)d_in[9];
    const float* bn_b_be  = (const float*)d_in[10];
    const float* bn_b_m   = (const float*)d_in[11];
    const float* bn_b_v   = (const float*)d_in[12];
    const float* att_a_w  = (const float*)d_in[13];
    const float* att_a_b  = (const float*)d_in[14];
    const float* att_b_w  = (const float*)d_in[15];
    const float* att_b_b  = (const float*)d_in[16];
    const float* abn_a_g  = (const float*)d_in[17];
    const float* abn_a_be = (const float*)d_in[18];
    const float* abn_a_m  = (const float*)d_in[19];
    const float* abn_a_v  = (const float*)d_in[20];
    const float* abn_b_g  = (const float*)d_in[21];
    const float* abn_b_be = (const float*)d_in[22];
    const float* abn_b_m  = (const float*)d_in[23];
    const float* abn_b_v  = (const float*)d_in[24];
    const float* attn_a_w = (const float*)d_in[25];
    const float* attn_b_w = (const float*)d_in[26];
    const float* scale1   = (const float*)d_in[27];
    const float* scale2   = (const float*)d_in[28];

    int B = in_sizes[0] / (CINc * HWC);

    cudaFuncSetAttribute(conv_mma_kernel,
                         cudaFuncAttributeMaxDynamicSharedMemorySize, SMEM_TOT);

    prep_x_kernel<<<B * 1024, 256>>>(x);
    prep_w_kernel<<<(18 * 128 * 64 + 255) / 256, 256>>>(conv_a_w, conv_b_w);

    conv_mma_kernel<<<B * 256, 512, SMEM_TOT>>>(
        conv_a_b, conv_b_b,
        bn_a_g, bn_a_be, bn_a_m, bn_a_v,
        bn_b_g, bn_b_be, bn_b_m, bn_b_v,
        att_a_w, att_a_b, att_b_w, att_b_b,
        abn_a_g, abn_a_be, abn_a_m, abn_a_v,
        abn_b_g, abn_b_be, abn_b_m, abn_b_v);

    int total = B * HWC;
    int nb = (total + 255) / 256;
    map_kernel<<<nb, 256>>>(attn_a_w, attn_b_w, scale1, scale2, B);

    int nb4 = (B * (HWC / 4) + 255) / 256;
    scale_kernel<<<nb4, 256>>>((float*)d_out, B);
}

// round 9
// speedup vs baseline: 7.5230x; 1.0422x over previous
#include <cuda_runtime.h>
#include <cuda_fp16.h>
#include <math.h>
#include <stdint.h>

#define Hc  256
#define Wc  256
#define CINc 128
#define HWC (Hc * Wc)

// ---------------- scratch (static device globals; no runtime allocation) ----
__device__ __align__(256) __half g_fh[(size_t)4 * 128 * HWC];  // post-BN features NCHW fp16
__device__ float g_att[(size_t)4 * 2 * HWC];                   // attention logits
__device__ float g_map[(size_t)4 * 2 * HWC];                   // sigmoid maps * scale
__device__ __align__(256) __half g_xh[(size_t)4 * HWC * 128];  // x fp16, NHWC
__device__ __align__(256) __half g_wh[18 * 128 * 64];          // W fp16 [chunk][oc][k]

// ---------------- helpers ----------------------------------------------------
__device__ __forceinline__ uint32_t smem_u32(const void* p) {
    uint32_t a;
    asm("{ .reg .u64 t; cvta.to.shared.u64 t, %1; cvt.u32.u64 %0, t; }" : "=r"(a) : "l"(p));
    return a;
}
__device__ __forceinline__ void cp16(uint32_t dst, const void* src, uint32_t sz) {
    asm volatile("cp.async.cg.shared.global [%0], [%1], 16, %2;"
                 :: "r"(dst), "l"(src), "r"(sz));
}
#define CP_COMMIT() asm volatile("cp.async.commit_group;" ::: "memory")
#define CP_WAIT2()  asm volatile("cp.async.wait_group 2;" ::: "memory")

__device__ __forceinline__ void ldsm_x4(uint32_t* r, uint32_t a) {
    asm volatile("ldmatrix.sync.aligned.m8n8.x4.shared.b16 {%0,%1,%2,%3}, [%4];"
                 : "=r"(r[0]), "=r"(r[1]), "=r"(r[2]), "=r"(r[3]) : "r"(a));
}
__device__ __forceinline__ void mma16816(float* d, const uint32_t* a, const uint32_t* b) {
    asm volatile("mma.sync.aligned.m16n8k16.row.col.f32.f16.f16.f32 "
                 "{%0,%1,%2,%3},{%4,%5,%6,%7},{%8,%9},{%0,%1,%2,%3};"
                 : "+f"(d[0]), "+f"(d[1]), "+f"(d[2]), "+f"(d[3])
                 : "r"(a[0]), "r"(a[1]), "r"(a[2]), "r"(a[3]), "r"(b[0]), "r"(b[1]));
}

// position helper (matches reference)
__device__ __forceinline__ float axis_g(int i, int n) {
    float off = ((n & 1) == 0) ? 0.5f : 0.0f;
    return fabsf((float)i - (float)(n / 2) + off) / (float)(n / 2);
}

// ============================================================================
// prep_x: NCHW fp32 -> NHWC fp16 (smem transpose, coalesced both sides)
// ============================================================================
__global__ __launch_bounds__(256)
void prep_x_kernel(const float* __restrict__ x)
{
    __shared__ __half s_h[64 * 136];
    int blk = blockIdx.x;
    int bb  = blk >> 10;
    int px0 = (blk & 1023) * 64;
    int tid = threadIdx.x;
    int p = tid & 63, cq = tid >> 6;

    const float* xb = x + (size_t)bb * CINc * HWC;
    for (int c0 = 0; c0 < CINc; c0 += 4) {
        int c = c0 + cq;
        s_h[p * 136 + c] = __float2half(xb[(size_t)c * HWC + px0 + p]);
    }
    __syncthreads();
    for (int i = tid; i < 64 * 16; i += 256) {
        int p2 = i >> 4, j = i & 15;
        uint4 v = *(const uint4*)&s_h[p2 * 136 + j * 8];
        size_t e = ((size_t)bb * HWC + px0 + p2) * 128 + j * 8;
        *(uint4*)(g_xh + e) = v;
    }
}

// ============================================================================
// prep_w: fp32 weights -> fp16, [chunk18][128oc][64k]
// ============================================================================
__global__ void prep_w_kernel(const float* __restrict__ wa, const float* __restrict__ wb)
{
    int idx = blockIdx.x * 256 + threadIdx.x;
    if (idx >= 18 * 128 * 64) return;
    int k  = idx & 63;
    int oc = (idx >> 6) & 127;
    int c  = idx >> 13;
    int t  = c >> 1, hf = c & 1;
    int cin = hf * 64 + k;
    float w = (oc < 64) ? wa[((size_t)oc * CINc + cin) * 9 + t]
                        : wb[((size_t)(oc - 64) * CINc + cin) * 9 + t];
    g_wh[idx] = __float2half(w);
}

// ============================================================================
// conv_mma: implicit GEMM via mma.sync fp16 (single term, fp32 accum)
//   CTA: 128 oc x 256 px (one full output row); 16 warps, warp tile 32x64
//   K: 18 chunks of 64 (tap x cin-half); cp.async 4-stage pipeline,
//   single barrier per chunk, loads issued before compute.
//   Epilogue: BN fold -> g_fh (fp16), PLUS fused 1x1 attention conv -> g_att
// ============================================================================
#define A_W  0
#define B_X  16384
#define STAGE 49152
#define SMEM_TOT (4 * STAGE)

// swizzled 16B offset inside a [row][64k] fp16 tile (row stride 128B)
__device__ __forceinline__ uint32_t swz(int row, int j16) {
    return (uint32_t)(row * 128 + ((j16 ^ (row & 7)) << 4));
}

__global__ __launch_bounds__(512, 1)
void conv_mma_kernel(const float* __restrict__ ba,  const float* __restrict__ bbv,
                     const float* __restrict__ gA,  const float* __restrict__ beA,
                     const float* __restrict__ mA,  const float* __restrict__ vA,
                     const float* __restrict__ gB,  const float* __restrict__ beB,
                     const float* __restrict__ mB,  const float* __restrict__ vB,
                     const float* __restrict__ aw,  const float* __restrict__ abv,
                     const float* __restrict__ bw,  const float* __restrict__ bb2,
                     const float* __restrict__ gA1, const float* __restrict__ beA1,
                     const float* __restrict__ mA1, const float* __restrict__ vA1,
                     const float* __restrict__ gB1, const float* __restrict__ beB1,
                     const float* __restrict__ mB1, const float* __restrict__ vB1)
{
    extern __shared__ char smem[];
    const uint32_t sb = smem_u32(smem);
    const int tid  = threadIdx.x;
    const int wid  = tid >> 5, lane = tid & 31;
    const int bb   = blockIdx.x >> 8;
    const int y    = blockIdx.x & 255;
    const int m0   = (wid >> 2) * 32;         // warp oc base (4 m-groups)
    const int n0   = (wid & 3) * 64;          // warp px base (4 n-groups)

    float C[2][8][4];
    #pragma unroll
    for (int mt = 0; mt < 2; mt++)
        #pragma unroll
        for (int nt = 0; nt < 8; nt++)
            #pragma unroll
            for (int q = 0; q < 4; q++) C[mt][nt][q] = 0.f;

    // ---- chunk loader: cp.async into stage (c & 3), one commit ----
    auto load_chunk = [&](int c) {
        uint32_t stg = sb + (uint32_t)(c & 3) * STAGE;
        int t  = c >> 1, hf = c & 1;
        int yy = y + t / 3 - 1;
        int dx = t % 3 - 1;
        bool vy = (yy >= 0) && (yy < Hc);
        size_t arow = (size_t)c * 8192;                       // A chunk base (elems)
        size_t brow = ((size_t)(bb * Hc + yy) * Wc) * 128;    // B row base (elems)
        #pragma unroll
        for (int i = 0; i < 2; i++) {                         // A: 128 oc rows
            int idx = tid + i * 512;
            int row = idx >> 3, j = idx & 7;
            cp16(stg + A_W + swz(row, j), g_wh + arow + idx * 8, 16);
        }
        #pragma unroll
        for (int i = 0; i < 4; i++) {                         // B: 256 px rows
            int idx = tid + i * 512;
            int row = idx >> 3, j = idx & 7;
            int xx = row + dx;
            bool ok = vy && (xx >= 0) && (xx < Wc);
            size_t e = ok ? (brow + (size_t)xx * 128 + hf * 64 + j * 8) : 0;
            cp16(stg + B_X + swz(row, j), g_xh + e, ok ? 16u : 0u);
        }
        CP_COMMIT();
    };

    // prologue: prefetch chunks 0..2
    load_chunk(0);
    load_chunk(1);
    load_chunk(2);

    for (int c = 0; c < 18; c++) {
        CP_WAIT2();                  // chunk c arrived (2 newer groups may fly)
        __syncthreads();             // all warps see stage (c&3); also fences
                                     // stage (c+3)&3 readers (compute c-1)
        if (c + 3 < 18) load_chunk(c + 3);   // in flight during compute(c)
        else            CP_COMMIT();         // uniform group accounting

        const uint32_t stg = sb + (uint32_t)(c & 3) * STAGE;
        #pragma unroll
        for (int kg = 0; kg < 4; kg++) {
            uint32_t ah[2][4];
            #pragma unroll
            for (int mt = 0; mt < 2; mt++) {
                int row = m0 + mt * 16 + (lane & 15);
                int kc  = kg * 2 + (lane >> 4);
                ldsm_x4(ah[mt], stg + A_W + swz(row, kc));
            }
            #pragma unroll
            for (int nq = 0; nq < 4; nq++) {
                uint32_t bx[4];
                int row = n0 + nq * 16 + (lane & 7) + ((lane >> 4) << 3);
                int kc  = kg * 2 + ((lane >> 3) & 1);
                ldsm_x4(bx, stg + B_X + swz(row, kc));
                #pragma unroll
                for (int mt = 0; mt < 2; mt++)
                    #pragma unroll
                    for (int h = 0; h < 2; h++)
                        mma16816(C[mt][nq * 2 + h], ah[mt], &bx[h * 2]);
            }
        }
    }
    __syncthreads();                 // all compute done before smem reuse (s_p)

    // ---- epilogue: BN fold -> g_fh (fp16), fused 1x1 att conv -> g_att ------
    float* s_p = (float*)smem;               // [4 m-groups][256 px] partials
    const int mg = wid >> 2;                 // m-group: 0,1 = branch a; 2,3 = b

    float scq4[2][2], sh4[2][2], wv4[2][2];
    __half* frow[2][2];
    #pragma unroll
    for (int mt = 0; mt < 2; mt++)
        #pragma unroll
        for (int hr = 0; hr < 2; hr++) {
            int oc = m0 + mt * 16 + (lane >> 2) + hr * 8;
            float sc, sh;
            if (oc < 64) {
                sc = gA[oc] * rsqrtf(vA[oc] + 1e-3f);
                sh = beA[oc] - mA[oc] * sc + ba[oc] * sc;
                wv4[mt][hr] = __ldg(aw + oc);
            } else {
                int o = oc - 64;
                sc = gB[o] * rsqrtf(vB[o] + 1e-3f);
                sh = beB[o] - mB[o] * sc + bbv[o] * sc;
                wv4[mt][hr] = __ldg(bw + o);
            }
            scq4[mt][hr] = sc;
            sh4[mt][hr]  = sh;
            frow[mt][hr] = g_fh + (((size_t)bb * 128 + oc) * Hc + y) * Wc;
        }

    #pragma unroll
    for (int nt = 0; nt < 8; nt++) {
        int col = n0 + nt * 8 + 2 * (lane & 3);
        float v0 = 0.f, v1 = 0.f;
        #pragma unroll
        for (int mt = 0; mt < 2; mt++)
            #pragma unroll
            for (int hr = 0; hr < 2; hr++) {
                float f0 = C[mt][nt][hr * 2 + 0] * scq4[mt][hr] + sh4[mt][hr];
                float f1 = C[mt][nt][hr * 2 + 1] * scq4[mt][hr] + sh4[mt][hr];
                *(__half2*)(frow[mt][hr] + col) = __floats2half2_rn(f0, f1);
                v0 += wv4[mt][hr] * f0;
                v1 += wv4[mt][hr] * f1;
            }
        // reduce across the 8 row-lanes (same lane&3)
        #pragma unroll
        for (int d = 16; d >= 4; d >>= 1) {
            v0 += __shfl_down_sync(0xffffffffu, v0, d);
            v1 += __shfl_down_sync(0xffffffffu, v1, d);
        }
        if ((lane >> 2) == 0) {
            s_p[mg * 256 + col]     = v0;
            s_p[mg * 256 + col + 1] = v1;
        }
    }
    __syncthreads();

    // finalize attention logits: +gh/gw terms +bias, BN, store (512 thr = 2x256)
    {
        int br = tid >> 8, col = tid & 255;
        float scA1 = __ldg(gA1) * rsqrtf(__ldg(vA1) + 1e-5f);
        float scB1 = __ldg(gB1) * rsqrtf(__ldg(vB1) + 1e-5f);
        float ghv  = axis_g(y, Hc);
        float gwv  = axis_g(col, Wc);
        float v = s_p[2 * br * 256 + col] + s_p[(2 * br + 1) * 256 + col];
        if (br == 0) {
            v += __ldg(aw + 64) * ghv + __ldg(aw + 65) * gwv + __ldg(abv);
            v = (v - __ldg(mA1)) * scA1 + __ldg(beA1);
        } else {
            v += __ldg(bw + 64) * ghv + __ldg(bw + 65) * gwv + __ldg(bb2);
            v = (v - __ldg(mB1)) * scB1 + __ldg(beB1);
        }
        g_att[((size_t)bb * 2 + br) * HWC + y * Wc + col] = v;
    }
}

// ============================================================================
// map_kernel: 3x3 conv over [att, gh, gw, pr] -> sigmoid * scale -> g_map
// ============================================================================
__global__ void map_kernel(const float* __restrict__ wA, const float* __restrict__ wB,
                           const float* __restrict__ s1p, const float* __restrict__ s2p,
                           int B)
{
    int idx = blockIdx.x * blockDim.x + threadIdx.x;
    int total = B * HWC;
    if (idx >= total) return;
    int bb  = idx / HWC;
    int pix = idx - bb * HWC;
    int y = pix / Wc;
    int x = pix - y * Wc;

    float ghmin = 0.5f / (float)(Hc / 2);
    float gwmin = 0.5f / (float)(Wc / 2);
    float ghmax = axis_g(0, Hc);
    float gwmax = axis_g(0, Wc);
    float prmin = sqrtf(ghmin * ghmin + gwmin * gwmin);
    float prmax = sqrtf(ghmax * ghmax + gwmax * gwmax);
    float kk = 2.f / (prmax - prmin);
    float cc = 1.f - prmax * kk;

    #pragma unroll
    for (int br = 0; br < 2; br++) {
        const float* w = br ? wB : wA;
        const float* ab = g_att + ((size_t)bb * 2 + br) * HWC;
        float s = 0.f;
        #pragma unroll
        for (int dy = -1; dy <= 1; dy++) {
            int yy = y + dy;
            if (yy < 0 || yy >= Hc) continue;
            float ghv = axis_g(yy, Hc);
            #pragma unroll
            for (int dxx = -1; dxx <= 1; dxx++) {
                int xn = x + dxx;
                if (xn < 0 || xn >= Wc) continue;
                float av  = ab[yy * Wc + xn];
                float gwv = axis_g(xn, Wc);
                float pr  = sqrtf(ghv * ghv + gwv * gwv);
                float prn = kk * pr + cc;
                int k = (dy + 1) * 3 + (dxx + 1);
                s += __ldg(w + k)      * av
                   + __ldg(w + 9 + k)  * ghv
                   + __ldg(w + 18 + k) * gwv
                   + __ldg(w + 27 + k) * prn;
            }
        }
        float m = 1.f / (1.f + expf(-s));
        g_map[((size_t)bb * 2 + br) * HWC + pix] =
            m * (br ? __ldg(s2p) : __ldg(s1p));
    }
}

// ============================================================================
// scale_kernel: out[c][p] = fp16(f)[c][p] * map[br][p]   (8 px / thread)
// ============================================================================
__global__ __launch_bounds__(256)
void scale_kernel(float* __restrict__ out, int B)
{
    int idx = blockIdx.x * blockDim.x + threadIdx.x;
    int total = B * (HWC / 8);
    if (idx >= total) return;
    int bb = idx / (HWC / 8);
    int p8 = (idx - bb * (HWC / 8)) * 8;

    float m[2][8];
    #pragma unroll
    for (int br = 0; br < 2; br++) {
        float4 a = *(const float4*)(g_map + ((size_t)bb * 2 + br) * HWC + p8);
        float4 b = *(const float4*)(g_map + ((size_t)bb * 2 + br) * HWC + p8 + 4);
        m[br][0] = a.x; m[br][1] = a.y; m[br][2] = a.z; m[br][3] = a.w;
        m[br][4] = b.x; m[br][5] = b.y; m[br][6] = b.z; m[br][7] = b.w;
    }

    const __half* f0 = g_fh + (size_t)bb * 128 * HWC + p8;
    float*        o0 = out  + (size_t)bb * 128 * HWC + p8;
    #pragma unroll 4
    for (int c = 0; c < 128; c++) {
        const float* mc = m[c >> 6];
        uint4 v = *(const uint4*)(f0 + (size_t)c * HWC);
        const __half2* h = (const __half2*)&v;
        float4 r0, r1;
        r0.x = __low2float(h[0])  * mc[0];
        r0.y = __high2float(h[0]) * mc[1];
        r0.z = __low2float(h[1])  * mc[2];
        r0.w = __high2float(h[1]) * mc[3];
        r1.x = __low2float(h[2])  * mc[4];
        r1.y = __high2float(h[2]) * mc[5];
        r1.z = __low2float(h[3])  * mc[6];
        r1.w = __high2float(h[3]) * mc[7];
        *(float4*)(o0 + (size_t)c * HWC)     = r0;
        *(float4*)(o0 + (size_t)c * HWC + 4) = r1;
    }
}

// ============================================================================
extern "C" void kernel_launch(void* const* d_in, const int* in_sizes, int n_in,
                              void* d_out, int out_size)
{
    const float* x        = (const float*)d_in[0];
    const float* conv_a_w = (const float*)d_in[1];
    const float* conv_a_b = (const float*)d_in[2];
    const float* conv_b_w = (const float*)d_in[3];
    const float* conv_b_b = (const float*)d_in[4];
    const float* bn_a_g   = (const float*)d_in[5];
    const float* bn_a_be  = (const float*)d_in[6];
    const float* bn_a_m   = (const float*)d_in[7];
    const float* bn_a_v   = (const float*)d_in[8];
    const float* bn_b_g   = (const float*)d_in[9];
    const float* bn_b_be  = (const float*)d_in[10];
    const float* bn_b_m   = (const float*)d_in[11];
    const float* bn_b_v   = (const float*)d_in[12];
    const float* att_a_w  = (const float*)d_in[13];
    const float* att_a_b  = (const float*)d_in[14];
    const float* att_b_w  = (const float*)d_in[15];
    const float* att_b_b  = (const float*)d_in[16];
    const float* abn_a_g  = (const float*)d_in[17];
    const float* abn_a_be = (const float*)d_in[18];
    const float* abn_a_m  = (const float*)d_in[19];
    const float* abn_a_v  = (const float*)d_in[20];
    const float* abn_b_g  = (const float*)d_in[21];
    const float* abn_b_be = (const float*)d_in[22];
    const float* abn_b_m  = (const float*)d_in[23];
    const float* abn_b_v  = (const float*)d_in[24];
    const float* attn_a_w = (const float*)d_in[25];
    const float* attn_b_w = (const float*)d_in[26];
    const float* scale1   = (const float*)d_in[27];
    const float* scale2   = (const float*)d_in[28];

    int B = in_sizes[0] / (CINc * HWC);

    cudaFuncSetAttribute(conv_mma_kernel,
                         cudaFuncAttributeMaxDynamicSharedMemorySize, SMEM_TOT);

    prep_x_kernel<<<B * 1024, 256>>>(x);
    prep_w_kernel<<<(18 * 128 * 64 + 255) / 256, 256>>>(conv_a_w, conv_b_w);

    conv_mma_kernel<<<B * 256, 512, SMEM_TOT>>>(
        conv_a_b, conv_b_b,
        bn_a_g, bn_a_be, bn_a_m, bn_a_v,
        bn_b_g, bn_b_be, bn_b_m, bn_b_v,
        att_a_w, att_a_b, att_b_w, att_b_b,
        abn_a_g, abn_a_be, abn_a_m, abn_a_v,
        abn_b_g, abn_b_be, abn_b_m, abn_b_v);

    int total = B * HWC;
    int nb = (total + 255) / 256;
    map_kernel<<<nb, 256>>>(attn_a_w, attn_b_w, scale1, scale2, B);

    int nb8 = (B * (HWC / 8) + 255) / 256;
    scale_kernel<<<nb8, 256>>>((float*)d_out, B);
}